// round 5
// baseline (speedup 1.0000x reference)
#include <cuda_runtime.h>
#include <cuda_bf16.h>
#include <stdint.h>

// ---------------------------------------------------------------------------
// Constants
// ---------------------------------------------------------------------------
#define MRR_A 0.987f
#define MRR_R 0.99f

#define OUT_CH 256
#define IN_CH  128
#define HW     56
#define HWP    58          // padded spatial
#define HWSQ   3136
#define KTOT   1152
#define PIXTOT 200704

#define NCHUNK  9          // one (r,s) position per chunk, K=128 channels
#define MT      128
#define NT      128
#define STAGES  3
#define NTHREADS 512

// fixed-point scales: x_q = x * 2^12, w_q = w * 2^14
// product = 2^-26 * (d1e1*65536 + (d1e2+d2e1)*256 + d2e2[dropped])
#define C_HI 9.765625e-4f        // 2^-10
#define C_MID 3.814697265625e-6f // 2^-18

// per-stage smem layout (bytes): 4 regions of 16KB (128 rows x 128B)
#define STG_BYTES 65536
#define SOFF_AD1  0
#define SOFF_AD2  16384
#define SOFF_BE1  32768
#define SOFF_BE2  49152
#define OFF_SCALE (STAGES * STG_BYTES)          // 196608
#define OFF_BIAS  (OFF_SCALE + 512)
#define SMEM_TOTAL (OFF_BIAS + 512)             // 197632

// ---------------------------------------------------------------------------
// Device-global scratch (zero-initialized -> halo stays zero forever)
// ---------------------------------------------------------------------------
__device__ __align__(256) int8_t g_xd1[64 * HWP * HWP * IN_CH];
__device__ __align__(256) int8_t g_xd2[64 * HWP * HWP * IN_CH];
__device__ __align__(256) int8_t g_wd1[OUT_CH * KTOT];   // [oc][rs][c]
__device__ __align__(256) int8_t g_wd2[OUT_CH * KTOT];
__device__ float g_scale[OUT_CH];
__device__ float g_bias[OUT_CH];

// ---------------------------------------------------------------------------
// Helpers
// ---------------------------------------------------------------------------
__device__ __forceinline__ uint32_t smem_u32(const void* p) {
    uint32_t a;
    asm("{ .reg .u64 t; cvta.to.shared.u64 t, %1; cvt.u32.u64 %0, t; }" : "=r"(a) : "l"(p));
    return a;
}
__device__ __forceinline__ uint32_t sw128(uint32_t off) {
    return off ^ ((off >> 3) & 0x70);
}
__device__ __forceinline__ void cp16(uint32_t dst, const int8_t* src) {
    asm volatile("cp.async.cg.shared.global [%0], [%1], 16;"
                 :: "r"(dst), "l"(__cvta_generic_to_global(src)));
}
#define CP_COMMIT() asm volatile("cp.async.commit_group;" ::: "memory")
#define CP_WAIT1()  asm volatile("cp.async.wait_group 1;" ::: "memory")

__device__ __forceinline__ void ldsm4(uint32_t* r, uint32_t addr) {
    asm volatile("ldmatrix.sync.aligned.m8n8.x4.shared.b16 {%0,%1,%2,%3}, [%4];"
                 : "=r"(r[0]), "=r"(r[1]), "=r"(r[2]), "=r"(r[3]) : "r"(addr));
}
__device__ __forceinline__ void mma_s8(int* d, const uint32_t* a, const uint32_t* b) {
    asm volatile(
        "mma.sync.aligned.m16n8k32.row.col.s32.s8.s8.s32 "
        "{%0,%1,%2,%3}, {%4,%5,%6,%7}, {%8,%9}, {%0,%1,%2,%3};"
        : "+r"(d[0]), "+r"(d[1]), "+r"(d[2]), "+r"(d[3])
        : "r"(a[0]), "r"(a[1]), "r"(a[2]), "r"(a[3]), "r"(b[0]), "r"(b[1]));
}

// ---------------------------------------------------------------------------
// Kernel 1: weights — MRR phase -> s8 digit pair in [oc][rs][c] order + BN fold
// ---------------------------------------------------------------------------
__global__ void prep_kernel(const float* __restrict__ phase,
                            const float* __restrict__ gamma,
                            const float* __restrict__ beta,
                            const float* __restrict__ rmean,
                            const float* __restrict__ rvar) {
    int idx = blockIdx.x * 256 + threadIdx.x;
    if (idx < OUT_CH * KTOT) {
        int oc  = idx / KTOT;
        int kp  = idx - oc * KTOT;     // rs*128 + c
        int rs  = kp >> 7;
        int c   = kp & 127;
        int korig = c * 9 + rs;        // original (c,r,s) K order used by the blocks
        int gy = oc >> 3, i = oc & 7;
        int gx = korig >> 3, j = korig & 7;
        float phi = phase[((gy * 144 + gx) * 8 + i) * 8 + j];
        float cc = cosf(phi);
        float ar = MRR_A * MRR_R;
        float num = MRR_A * MRR_A - 2.0f * ar * cc + MRR_R * MRR_R;
        float den = 1.0f - 2.0f * ar * cc + ar * ar;
        float tr = num / den;          // in (0.016, 1.0)
        int wq = (int)lrintf(tr * 16384.0f);
        if (wq > 16384) wq = 16384;
        if (wq < 0) wq = 0;
        int e1 = (wq + 128) >> 8;      // [0, 64]
        int e2 = wq - (e1 << 8);       // [-128, 127]
        g_wd1[idx] = (int8_t)e1;
        g_wd2[idx] = (int8_t)e2;
    }
    if (idx < OUT_CH) {
        float inv = gamma[idx] * rsqrtf(rvar[idx] + 1e-5f);
        g_scale[idx] = inv;
        g_bias[idx]  = beta[idx] - rmean[idx] * inv;
    }
}

// ---------------------------------------------------------------------------
// Kernel 2: x NCHW fp32 -> padded NHWC s8 digit pair (smem transpose)
// ---------------------------------------------------------------------------
__global__ void __launch_bounds__(256)
xprep_kernel(const float* __restrict__ x) {
    __shared__ float tile[IN_CH][HW + 1];
    const int n = blockIdx.x, h = blockIdx.y;
    const int tid = threadIdx.x;
    const float* xb = x + (size_t)n * IN_CH * HWSQ + h * HW;
    #pragma unroll 4
    for (int i = tid; i < IN_CH * HW; i += 256) {
        int c = i / HW, w = i - c * HW;
        tile[c][w] = xb[(size_t)c * HWSQ + w];
    }
    __syncthreads();
    const size_t obase = (((size_t)n * HWP + h + 1) * HWP + 1) * IN_CH;
    #pragma unroll 4
    for (int i = tid; i < HW * IN_CH; i += 256) {
        int w = i >> 7, c = i & 127;
        float v = tile[c][w];
        int xq = (int)lrintf(v * 4096.0f);
        if (xq > 32639) xq = 32639;
        if (xq < -32768) xq = -32768;
        int d1 = (xq + 128) >> 8;      // [-128, 127]
        int d2 = xq - (d1 << 8);       // [-128, 127]
        g_xd1[obase + (size_t)w * IN_CH + c] = (int8_t)d1;
        g_xd2[obase + (size_t)w * IN_CH + c] = (int8_t)d2;
    }
}

// ---------------------------------------------------------------------------
// Kernel 3: implicit-GEMM conv, cp.async 3-stage pipeline, s8 double-digit mma
//   512 threads, warp grid 4x4, warp tile 32x32
// ---------------------------------------------------------------------------
__global__ void __launch_bounds__(NTHREADS, 1)
conv_kernel(float* __restrict__ out) {
    extern __shared__ char smem[];
    const uint32_t sb = smem_u32(smem);
    const int tid = threadIdx.x;
    const int wid = tid >> 5;
    const int lid = tid & 31;
    const int p0  = blockIdx.x * MT;
    const int oc0 = blockIdx.y * NT;

    const int warpM = wid >> 2;        // 0..3 -> 32-pixel band
    const int warpN = wid & 3;         // 0..3 -> 32-oc band

    if (tid < NT) {
        ((float*)(smem + OFF_SCALE))[tid] = g_scale[oc0 + tid];
        ((float*)(smem + OFF_BIAS))[tid]  = g_bias[oc0 + tid];
    }

    // ---- per-thread load assignment: 4 threads per 128B row, 2 segs each --
    const int lrow = tid >> 2;                 // 0..127 (pixel row & oc row)
    const int segb = (tid & 3) * 2;            // 16B-segment start (of 8)
    const int pg   = p0 + lrow;
    const int nimg = pg / HWSQ;
    const int rem  = pg - nimg * HWSQ;
    const int oh   = rem / HW;
    const int ow   = rem - oh * HW;
    const int8_t* xd1_n = g_xd1 + (size_t)nimg * (HWP * HWP * IN_CH);
    const int8_t* xd2_n = g_xd2 + (size_t)nimg * (HWP * HWP * IN_CH);
    uint32_t dsts[2];
    #pragma unroll
    for (int j = 0; j < 2; ++j)
        dsts[j] = sw128((uint32_t)(lrow * 128 + (segb + j) * 16));

    auto issue_loads = [&](int rs, int st) {
        const int r = rs / 3, s = rs - r * 3;
        const size_t aoff = (((size_t)(oh + r) * HWP) + (ow + s)) * IN_CH + segb * 16;
        const int8_t* a1 = xd1_n + aoff;
        const int8_t* a2 = xd2_n + aoff;
        const size_t boff = ((size_t)(oc0 + lrow) * 9 + rs) * 128 + segb * 16;
        const int8_t* b1 = g_wd1 + boff;
        const int8_t* b2 = g_wd2 + boff;
        const uint32_t s0 = sb + st * STG_BYTES;
        #pragma unroll
        for (int j = 0; j < 2; ++j) {
            cp16(s0 + SOFF_AD1 + dsts[j], a1 + j * 16);
            cp16(s0 + SOFF_AD2 + dsts[j], a2 + j * 16);
            cp16(s0 + SOFF_BE1 + dsts[j], b1 + j * 16);
            cp16(s0 + SOFF_BE2 + dsts[j], b2 + j * 16);
        }
    };

    int acch[2][4][4], accm[2][4][4];
    #pragma unroll
    for (int f = 0; f < 2; ++f)
        #pragma unroll
        for (int g = 0; g < 4; ++g)
            #pragma unroll
            for (int e = 0; e < 4; ++e) { acch[f][g][e] = 0; accm[f][g][e] = 0; }

    // ldmatrix lane mapping (s8 k32 fragments)
    const int li = lid >> 3;           // 0..3
    const int lj = lid & 7;
    // A: matrices (rows0-7,k0-15)(rows8-15,k0-15)(rows0-7,k16-31)(rows8-15,k16-31)
    const int a_row = warpM * 32 + (li & 1) * 8 + lj;
    const int a_kb  = (li >> 1) * 16;
    // B: matrices (oc0-7,k0-15)(oc0-7,k16-31)(oc8-15,k0-15)(oc8-15,k16-31)
    const int b_row = warpN * 32 + (li >> 1) * 8 + lj;
    const int b_kb  = (li & 1) * 16;

    // ---- pipeline prologue ----
    issue_loads(0, 0); CP_COMMIT();
    issue_loads(1, 1); CP_COMMIT();

    for (int kc = 0; kc < NCHUNK; ++kc) {
        CP_WAIT1();            // stage kc resident
        __syncthreads();       // all warps done reading stage (kc-1)%3

        const int kn = kc + (STAGES - 1);
        if (kn < NCHUNK) issue_loads(kn, kn % STAGES);
        CP_COMMIT();

        const uint32_t s0 = sb + (kc % STAGES) * STG_BYTES;
        #pragma unroll
        for (int ks = 0; ks < 4; ++ks) {
            uint32_t Ad1[2][4], Ad2[2][4], Be1[4][2], Be2[4][2];
            #pragma unroll
            for (int f = 0; f < 2; ++f) {
                uint32_t off = sw128((uint32_t)((a_row + f * 16) * 128 +
                                                ks * 32 + a_kb));
                ldsm4(Ad1[f], s0 + SOFF_AD1 + off);
                ldsm4(Ad2[f], s0 + SOFF_AD2 + off);
            }
            #pragma unroll
            for (int h = 0; h < 2; ++h) {
                uint32_t off = sw128((uint32_t)((b_row + h * 16) * 128 +
                                                ks * 32 + b_kb));
                uint32_t t[4];
                ldsm4(t, s0 + SOFF_BE1 + off);
                Be1[h*2+0][0] = t[0]; Be1[h*2+0][1] = t[1];
                Be1[h*2+1][0] = t[2]; Be1[h*2+1][1] = t[3];
                ldsm4(t, s0 + SOFF_BE2 + off);
                Be2[h*2+0][0] = t[0]; Be2[h*2+0][1] = t[1];
                Be2[h*2+1][0] = t[2]; Be2[h*2+1][1] = t[3];
            }
            #pragma unroll
            for (int f = 0; f < 2; ++f)
                #pragma unroll
                for (int g = 0; g < 4; ++g) {
                    mma_s8(acch[f][g], Ad1[f], Be1[g]);
                    mma_s8(accm[f][g], Ad1[f], Be2[g]);
                    mma_s8(accm[f][g], Ad2[f], Be1[g]);
                }
        }
    }

    // ---- epilogue: combine digits + BN + ReLU6 + stores -------------------
    const float* ss = (const float*)(smem + OFF_SCALE);
    const float* bb = (const float*)(smem + OFF_BIAS);

    #pragma unroll
    for (int f = 0; f < 2; ++f) {
        int p1 = p0 + warpM * 32 + f * 16 + (lid >> 2);
        int p2 = p1 + 8;
        int n1 = p1 / HWSQ, r1 = p1 - n1 * HWSQ;
        int n2 = p2 / HWSQ, r2 = p2 - n2 * HWSQ;
        float* o1 = out + (size_t)n1 * OUT_CH * HWSQ + r1;
        float* o2 = out + (size_t)n2 * OUT_CH * HWSQ + r2;
        #pragma unroll
        for (int g = 0; g < 4; ++g) {
            int cl = warpN * 32 + g * 8 + (lid & 3) * 2;
            int ocA = oc0 + cl, ocB = ocA + 1;
            float sA = ss[cl], bA = bb[cl];
            float sB = ss[cl + 1], bB = bb[cl + 1];
            float y0 = (float)acch[f][g][0] * C_HI + (float)accm[f][g][0] * C_MID;
            float y1 = (float)acch[f][g][1] * C_HI + (float)accm[f][g][1] * C_MID;
            float y2 = (float)acch[f][g][2] * C_HI + (float)accm[f][g][2] * C_MID;
            float y3 = (float)acch[f][g][3] * C_HI + (float)accm[f][g][3] * C_MID;
            float v0 = fminf(fmaxf(y0 * sA + bA, 0.0f), 6.0f);
            float v1 = fminf(fmaxf(y1 * sB + bB, 0.0f), 6.0f);
            float v2 = fminf(fmaxf(y2 * sA + bA, 0.0f), 6.0f);
            float v3 = fminf(fmaxf(y3 * sB + bB, 0.0f), 6.0f);
            o1[(size_t)ocA * HWSQ] = v0;
            o1[(size_t)ocB * HWSQ] = v1;
            o2[(size_t)ocA * HWSQ] = v2;
            o2[(size_t)ocB * HWSQ] = v3;
        }
    }
}

// ---------------------------------------------------------------------------
// Launch
// ---------------------------------------------------------------------------
extern "C" void kernel_launch(void* const* d_in, const int* in_sizes, int n_in,
                              void* d_out, int out_size) {
    const float* x     = (const float*)d_in[0];
    const float* phase = (const float*)d_in[1];
    const float* gamma = (const float*)d_in[2];
    const float* beta  = (const float*)d_in[3];
    const float* rmean = (const float*)d_in[4];
    const float* rvar  = (const float*)d_in[5];
    float* out = (float*)d_out;

    cudaFuncSetAttribute(conv_kernel,
                         cudaFuncAttributeMaxDynamicSharedMemorySize, SMEM_TOTAL);

    prep_kernel<<<(OUT_CH * KTOT + 255) / 256, 256>>>(phase, gamma, beta, rmean, rvar);
    dim3 xg(64, HW);
    xprep_kernel<<<xg, 256>>>(x);

    dim3 grid(PIXTOT / MT, OUT_CH / NT);   // (1568, 2)
    conv_kernel<<<grid, NTHREADS, SMEM_TOTAL>>>(out);
}

// round 6
// speedup vs baseline: 2.2658x; 2.2658x over previous
#include <cuda_runtime.h>
#include <cuda_bf16.h>
#include <stdint.h>

// ---------------------------------------------------------------------------
// Constants
// ---------------------------------------------------------------------------
#define MRR_A 0.987f
#define MRR_R 0.99f

#define OUT_CH 256
#define IN_CH  128
#define HW     56
#define HWP    58          // padded spatial
#define HWSQ   3136
#define KTOT   1152
#define PIXTOT 200704

#define KC      64
#define NCHUNK  18         // 9 (r,s) positions x 2 channel-halves
#define MT      128
#define NT      128
#define STAGES  3
#define NTHREADS 256       // 8 warps, grid 2x4, warp tile 64x32

// per-stage smem layout (bytes)
#define STG_BYTES 65536
#define SOFF_AHI  0
#define SOFF_ALO  16384
#define SOFF_BHI  32768
#define SOFF_BLO  49152
#define OFF_SCALE (STAGES * STG_BYTES)          // 196608
#define OFF_BIAS  (OFF_SCALE + 512)
#define SMEM_TOTAL (OFF_BIAS + 512)             // 197632

// ---------------------------------------------------------------------------
// Device-global scratch (zero-initialized -> halo stays zero forever)
// ---------------------------------------------------------------------------
__device__ __align__(256) __nv_bfloat16 g_x_hi[64 * HWP * HWP * IN_CH];
__device__ __align__(256) __nv_bfloat16 g_x_lo[64 * HWP * HWP * IN_CH];
__device__ __align__(256) __nv_bfloat16 g_w_hi[OUT_CH * KTOT];   // [oc][rs][c]
__device__ __align__(256) __nv_bfloat16 g_w_lo[OUT_CH * KTOT];
__device__ float g_scale[OUT_CH];
__device__ float g_bias[OUT_CH];

// ---------------------------------------------------------------------------
// Helpers
// ---------------------------------------------------------------------------
__device__ __forceinline__ uint32_t smem_u32(const void* p) {
    uint32_t a;
    asm("{ .reg .u64 t; cvta.to.shared.u64 t, %1; cvt.u32.u64 %0, t; }" : "=r"(a) : "l"(p));
    return a;
}
__device__ __forceinline__ uint32_t sw128(uint32_t off) {
    return off ^ ((off >> 3) & 0x70);
}
__device__ __forceinline__ void cp16(uint32_t dst, const __nv_bfloat16* src) {
    asm volatile("cp.async.cg.shared.global [%0], [%1], 16;"
                 :: "r"(dst), "l"(__cvta_generic_to_global(src)));
}
#define CP_COMMIT() asm volatile("cp.async.commit_group;" ::: "memory")
#define CP_WAIT1()  asm volatile("cp.async.wait_group 1;" ::: "memory")

__device__ __forceinline__ void ldsm4(uint32_t* r, uint32_t addr) {
    asm volatile("ldmatrix.sync.aligned.m8n8.x4.shared.b16 {%0,%1,%2,%3}, [%4];"
                 : "=r"(r[0]), "=r"(r[1]), "=r"(r[2]), "=r"(r[3]) : "r"(addr));
}
__device__ __forceinline__ void mma16816(float* d, const uint32_t* a, const uint32_t* b) {
    asm volatile(
        "mma.sync.aligned.m16n8k16.row.col.f32.bf16.bf16.f32 "
        "{%0,%1,%2,%3}, {%4,%5,%6,%7}, {%8,%9}, {%0,%1,%2,%3};"
        : "+f"(d[0]), "+f"(d[1]), "+f"(d[2]), "+f"(d[3])
        : "r"(a[0]), "r"(a[1]), "r"(a[2]), "r"(a[3]), "r"(b[0]), "r"(b[1]));
}

// ---------------------------------------------------------------------------
// Kernel 1: weights — MRR phase -> bf16 hi/lo in [oc][rs][c] order + BN fold
// ---------------------------------------------------------------------------
__global__ void prep_kernel(const float* __restrict__ phase,
                            const float* __restrict__ gamma,
                            const float* __restrict__ beta,
                            const float* __restrict__ rmean,
                            const float* __restrict__ rvar) {
    int idx = blockIdx.x * 256 + threadIdx.x;
    if (idx < OUT_CH * KTOT) {
        int oc  = idx / KTOT;
        int kp  = idx - oc * KTOT;     // rs*128 + c
        int rs  = kp >> 7;
        int c   = kp & 127;
        int korig = c * 9 + rs;        // original (c,r,s) K order used by the blocks
        int gy = oc >> 3, i = oc & 7;
        int gx = korig >> 3, j = korig & 7;
        float phi = phase[((gy * 144 + gx) * 8 + i) * 8 + j];
        float cc = cosf(phi);
        float ar = MRR_A * MRR_R;
        float num = MRR_A * MRR_A - 2.0f * ar * cc + MRR_R * MRR_R;
        float den = 1.0f - 2.0f * ar * cc + ar * ar;
        float tr = num / den;
        __nv_bfloat16 hi = __float2bfloat16(tr);
        g_w_hi[idx] = hi;
        g_w_lo[idx] = __float2bfloat16(tr - __bfloat162float(hi));
    }
    if (idx < OUT_CH) {
        float inv = gamma[idx] * rsqrtf(rvar[idx] + 1e-5f);
        g_scale[idx] = inv;
        g_bias[idx]  = beta[idx] - rmean[idx] * inv;
    }
}

// ---------------------------------------------------------------------------
// Kernel 2: x NCHW fp32 -> padded NHWC bf16 hi/lo (smem transpose)
// ---------------------------------------------------------------------------
__global__ void __launch_bounds__(256)
xprep_kernel(const float* __restrict__ x) {
    __shared__ float tile[IN_CH][HW + 1];
    const int n = blockIdx.x, h = blockIdx.y;
    const int tid = threadIdx.x;
    const float* xb = x + (size_t)n * IN_CH * HWSQ + h * HW;
    #pragma unroll 4
    for (int i = tid; i < IN_CH * HW; i += 256) {
        int c = i / HW, w = i - c * HW;
        tile[c][w] = xb[(size_t)c * HWSQ + w];
    }
    __syncthreads();
    const size_t obase = (((size_t)n * HWP + h + 1) * HWP + 1) * IN_CH;
    #pragma unroll 4
    for (int i = tid; i < HW * IN_CH; i += 256) {
        int w = i >> 7, c = i & 127;
        float v = tile[c][w];
        __nv_bfloat16 hi = __float2bfloat16(v);
        g_x_hi[obase + (size_t)w * IN_CH + c] = hi;
        g_x_lo[obase + (size_t)w * IN_CH + c] = __float2bfloat16(v - __bfloat162float(hi));
    }
}

// ---------------------------------------------------------------------------
// Kernel 3: implicit-GEMM conv, cp.async 3-stage pipeline, bf16x3 mma.sync
//   256 threads, 8 warps (2x4), warp tile 64x32, fragment double-buffering
// ---------------------------------------------------------------------------
__global__ void __launch_bounds__(NTHREADS, 1)
conv_kernel(float* __restrict__ out) {
    extern __shared__ char smem[];
    const uint32_t sb = smem_u32(smem);
    const int tid = threadIdx.x;
    const int wid = tid >> 5;
    const int lid = tid & 31;
    const int p0  = blockIdx.x * MT;
    const int oc0 = blockIdx.y * NT;

    const int warpM = wid >> 2;        // 0..1 -> 64-pixel band
    const int warpN = wid & 3;         // 0..3 -> 32-oc band

    if (tid < NT) {
        ((float*)(smem + OFF_SCALE))[tid] = g_scale[oc0 + tid];
        ((float*)(smem + OFF_BIAS))[tid]  = g_bias[oc0 + tid];
    }

    // ---- per-thread load assignment: 2 threads per 128B row, 4 segs each --
    const int lrow = tid >> 1;                 // 0..127 (pixel row & oc row)
    const int segb = (tid & 1) * 4;            // 16B-segment start (of 8)
    const int pg   = p0 + lrow;
    const int nimg = pg / HWSQ;
    const int rem  = pg - nimg * HWSQ;
    const int oh   = rem / HW;
    const int ow   = rem - oh * HW;
    const __nv_bfloat16* xhi_n = g_x_hi + (size_t)nimg * (HWP * HWP * IN_CH);
    const __nv_bfloat16* xlo_n = g_x_lo + (size_t)nimg * (HWP * HWP * IN_CH);
    uint32_t dsts[4];
    #pragma unroll
    for (int j = 0; j < 4; ++j)
        dsts[j] = sw128((uint32_t)(lrow * 128 + (segb + j) * 16));

    auto issue_loads = [&](int kc, int st) {
        const int rs = kc >> 1, half = kc & 1;
        const int r = rs / 3, s = rs - r * 3;
        const size_t aoff = (((size_t)(oh + r) * HWP) + (ow + s)) * IN_CH
                            + half * 64 + segb * 8;
        const __nv_bfloat16* ahi = xhi_n + aoff;
        const __nv_bfloat16* alo = xlo_n + aoff;
        const size_t boff = ((size_t)(oc0 + lrow) * 9 + rs) * 128
                            + half * 64 + segb * 8;
        const __nv_bfloat16* bhi = g_w_hi + boff;
        const __nv_bfloat16* blo = g_w_lo + boff;
        const uint32_t s0 = sb + st * STG_BYTES;
        #pragma unroll
        for (int j = 0; j < 4; ++j) {
            cp16(s0 + SOFF_AHI + dsts[j], ahi + j * 8);
            cp16(s0 + SOFF_ALO + dsts[j], alo + j * 8);
            cp16(s0 + SOFF_BHI + dsts[j], bhi + j * 8);
            cp16(s0 + SOFF_BLO + dsts[j], blo + j * 8);
        }
    };

    float acc[4][4][4];
    #pragma unroll
    for (int f = 0; f < 4; ++f)
        #pragma unroll
        for (int g = 0; g < 4; ++g)
            #pragma unroll
            for (int e = 0; e < 4; ++e) acc[f][g][e] = 0.0f;

    // ldmatrix lane mapping
    const int li = lid >> 3;
    const int lj = lid & 7;
    const int a_row = warpM * 64 + (li & 1) * 8 + lj;
    const int a_kof = (li >> 1) * 8;
    const int b_row = warpN * 32 + (li >> 1) * 8 + lj;
    const int b_kof = (li & 1) * 8;

    // double-buffered fragments
    uint32_t Ahi[2][4][4], Alo[2][4][4], Bhi[2][4][2], Blo[2][4][2];

    // ---- pipeline prologue ----
    issue_loads(0, 0); CP_COMMIT();
    issue_loads(1, 1); CP_COMMIT();

    for (int kc = 0; kc < NCHUNK; ++kc) {
        CP_WAIT1();            // stage kc resident
        __syncthreads();       // all warps done reading stage (kc-1)%3

        const int kn = kc + (STAGES - 1);
        if (kn < NCHUNK) issue_loads(kn, kn % STAGES);
        CP_COMMIT();

        const uint32_t s0 = sb + (kc % STAGES) * STG_BYTES;

        // load ks=0 fragments into buffer 0
        {
            #pragma unroll
            for (int f = 0; f < 4; ++f) {
                uint32_t off = sw128((uint32_t)((a_row + f * 16) * 128 + a_kof * 2));
                ldsm4(Ahi[0][f], s0 + SOFF_AHI + off);
                ldsm4(Alo[0][f], s0 + SOFF_ALO + off);
            }
            #pragma unroll
            for (int h = 0; h < 2; ++h) {
                uint32_t off = sw128((uint32_t)((b_row + h * 16) * 128 + b_kof * 2));
                uint32_t t[4];
                ldsm4(t, s0 + SOFF_BHI + off);
                Bhi[0][h*2+0][0] = t[0]; Bhi[0][h*2+0][1] = t[1];
                Bhi[0][h*2+1][0] = t[2]; Bhi[0][h*2+1][1] = t[3];
                ldsm4(t, s0 + SOFF_BLO + off);
                Blo[0][h*2+0][0] = t[0]; Blo[0][h*2+0][1] = t[1];
                Blo[0][h*2+1][0] = t[2]; Blo[0][h*2+1][1] = t[3];
            }
        }

        #pragma unroll
        for (int ks = 0; ks < 4; ++ks) {
            const int cur = ks & 1;
            const int nxt = cur ^ 1;
            if (ks < 3) {
                // prefetch ks+1 fragments into the other buffer
                #pragma unroll
                for (int f = 0; f < 4; ++f) {
                    uint32_t off = sw128((uint32_t)((a_row + f * 16) * 128 +
                                                    ((ks + 1) * 16 + a_kof) * 2));
                    ldsm4(Ahi[nxt][f], s0 + SOFF_AHI + off);
                    ldsm4(Alo[nxt][f], s0 + SOFF_ALO + off);
                }
                #pragma unroll
                for (int h = 0; h < 2; ++h) {
                    uint32_t off = sw128((uint32_t)((b_row + h * 16) * 128 +
                                                    ((ks + 1) * 16 + b_kof) * 2));
                    uint32_t t[4];
                    ldsm4(t, s0 + SOFF_BHI + off);
                    Bhi[nxt][h*2+0][0] = t[0]; Bhi[nxt][h*2+0][1] = t[1];
                    Bhi[nxt][h*2+1][0] = t[2]; Bhi[nxt][h*2+1][1] = t[3];
                    ldsm4(t, s0 + SOFF_BLO + off);
                    Blo[nxt][h*2+0][0] = t[0]; Blo[nxt][h*2+0][1] = t[1];
                    Blo[nxt][h*2+1][0] = t[2]; Blo[nxt][h*2+1][1] = t[3];
                }
            }
            #pragma unroll
            for (int f = 0; f < 4; ++f)
                #pragma unroll
                for (int g = 0; g < 4; ++g) {
                    mma16816(acc[f][g], Ahi[cur][f], Bhi[cur][g]);
                    mma16816(acc[f][g], Ahi[cur][f], Blo[cur][g]);
                    mma16816(acc[f][g], Alo[cur][f], Bhi[cur][g]);
                }
        }
    }

    // ---- epilogue: BN + ReLU6 + stores ------------------------------------
    const float* ss = (const float*)(smem + OFF_SCALE);
    const float* bb = (const float*)(smem + OFF_BIAS);

    #pragma unroll
    for (int f = 0; f < 4; ++f) {
        int p1 = p0 + warpM * 64 + f * 16 + (lid >> 2);
        int p2 = p1 + 8;
        int n1 = p1 / HWSQ, r1 = p1 - n1 * HWSQ;
        int n2 = p2 / HWSQ, r2 = p2 - n2 * HWSQ;
        float* o1 = out + (size_t)n1 * OUT_CH * HWSQ + r1;
        float* o2 = out + (size_t)n2 * OUT_CH * HWSQ + r2;
        #pragma unroll
        for (int g = 0; g < 4; ++g) {
            int cl = warpN * 32 + g * 8 + (lid & 3) * 2;
            int ocA = oc0 + cl, ocB = ocA + 1;
            float sA = ss[cl], bA = bb[cl];
            float sB = ss[cl + 1], bB = bb[cl + 1];
            float v0 = fminf(fmaxf(acc[f][g][0] * sA + bA, 0.0f), 6.0f);
            float v1 = fminf(fmaxf(acc[f][g][1] * sB + bB, 0.0f), 6.0f);
            float v2 = fminf(fmaxf(acc[f][g][2] * sA + bA, 0.0f), 6.0f);
            float v3 = fminf(fmaxf(acc[f][g][3] * sB + bB, 0.0f), 6.0f);
            o1[(size_t)ocA * HWSQ] = v0;
            o1[(size_t)ocB * HWSQ] = v1;
            o2[(size_t)ocA * HWSQ] = v2;
            o2[(size_t)ocB * HWSQ] = v3;
        }
    }
}

// ---------------------------------------------------------------------------
// Launch
// ---------------------------------------------------------------------------
extern "C" void kernel_launch(void* const* d_in, const int* in_sizes, int n_in,
                              void* d_out, int out_size) {
    const float* x     = (const float*)d_in[0];
    const float* phase = (const float*)d_in[1];
    const float* gamma = (const float*)d_in[2];
    const float* beta  = (const float*)d_in[3];
    const float* rmean = (const float*)d_in[4];
    const float* rvar  = (const float*)d_in[5];
    float* out = (float*)d_out;

    cudaFuncSetAttribute(conv_kernel,
                         cudaFuncAttributeMaxDynamicSharedMemorySize, SMEM_TOTAL);

    prep_kernel<<<(OUT_CH * KTOT + 255) / 256, 256>>>(phase, gamma, beta, rmean, rvar);
    dim3 xg(64, HW);
    xprep_kernel<<<xg, 256>>>(x);

    dim3 grid(PIXTOT / MT, OUT_CH / NT);   // (1568, 2)
    conv_kernel<<<grid, NTHREADS, SMEM_TOTAL>>>(out);
}

// round 7
// speedup vs baseline: 2.5614x; 1.1304x over previous
#include <cuda_runtime.h>
#include <cuda_bf16.h>
#include <stdint.h>

// ---------------------------------------------------------------------------
// Constants
// ---------------------------------------------------------------------------
#define MRR_A 0.987f
#define MRR_R 0.99f

#define OUT_CH 256
#define IN_CH  128
#define HW     56
#define HWP    58          // padded spatial
#define HWSQ   3136
#define KTOT   1152
#define PIXTOT 200704

#define KC      64
#define NCHUNK  18         // 9 (r,s) positions x 2 channel-halves
#define MT      128
#define NT      128
#define STAGES  3
#define NTHREADS 512       // 16 warps, grid 4x4, warp tile 32x32

// per-stage smem layout (bytes)
#define STG_BYTES 65536
#define SOFF_AHI  0
#define SOFF_ALO  16384
#define SOFF_BHI  32768
#define SOFF_BLO  49152
#define OFF_SCALE (STAGES * STG_BYTES)          // 196608
#define OFF_BIAS  (OFF_SCALE + 512)
#define SMEM_TOTAL (OFF_BIAS + 512)             // 197632

// ---------------------------------------------------------------------------
// Device-global scratch (zero-initialized -> halo stays zero forever)
// ---------------------------------------------------------------------------
__device__ __align__(256) __nv_bfloat16 g_x_hi[64 * HWP * HWP * IN_CH];
__device__ __align__(256) __nv_bfloat16 g_x_lo[64 * HWP * HWP * IN_CH];
__device__ __align__(256) __nv_bfloat16 g_w_hi[OUT_CH * KTOT];   // [oc][rs][c]
__device__ __align__(256) __nv_bfloat16 g_w_lo[OUT_CH * KTOT];
__device__ float g_scale[OUT_CH];
__device__ float g_bias[OUT_CH];

// ---------------------------------------------------------------------------
// Helpers
// ---------------------------------------------------------------------------
__device__ __forceinline__ uint32_t smem_u32(const void* p) {
    uint32_t a;
    asm("{ .reg .u64 t; cvta.to.shared.u64 t, %1; cvt.u32.u64 %0, t; }" : "=r"(a) : "l"(p));
    return a;
}
__device__ __forceinline__ uint32_t sw128(uint32_t off) {
    return off ^ ((off >> 3) & 0x70);
}
__device__ __forceinline__ void cp16(uint32_t dst, const __nv_bfloat16* src) {
    asm volatile("cp.async.cg.shared.global [%0], [%1], 16;"
                 :: "r"(dst), "l"(__cvta_generic_to_global(src)));
}
#define CP_COMMIT() asm volatile("cp.async.commit_group;" ::: "memory")
#define CP_WAIT1()  asm volatile("cp.async.wait_group 1;" ::: "memory")

__device__ __forceinline__ void ldsm4(uint32_t* r, uint32_t addr) {
    asm volatile("ldmatrix.sync.aligned.m8n8.x4.shared.b16 {%0,%1,%2,%3}, [%4];"
                 : "=r"(r[0]), "=r"(r[1]), "=r"(r[2]), "=r"(r[3]) : "r"(addr));
}
__device__ __forceinline__ void mma16816(float* d, const uint32_t* a, const uint32_t* b) {
    asm volatile(
        "mma.sync.aligned.m16n8k16.row.col.f32.bf16.bf16.f32 "
        "{%0,%1,%2,%3}, {%4,%5,%6,%7}, {%8,%9}, {%0,%1,%2,%3};"
        : "+f"(d[0]), "+f"(d[1]), "+f"(d[2]), "+f"(d[3])
        : "r"(a[0]), "r"(a[1]), "r"(a[2]), "r"(a[3]), "r"(b[0]), "r"(b[1]));
}

// ---------------------------------------------------------------------------
// Kernel 1: weights — MRR phase -> bf16 hi/lo in [oc][rs][c] order + BN fold
// ---------------------------------------------------------------------------
__global__ void prep_kernel(const float* __restrict__ phase,
                            const float* __restrict__ gamma,
                            const float* __restrict__ beta,
                            const float* __restrict__ rmean,
                            const float* __restrict__ rvar) {
    int idx = blockIdx.x * 256 + threadIdx.x;
    if (idx < OUT_CH * KTOT) {
        int oc  = idx / KTOT;
        int kp  = idx - oc * KTOT;     // rs*128 + c
        int rs  = kp >> 7;
        int c   = kp & 127;
        int korig = c * 9 + rs;        // original (c,r,s) K order used by the blocks
        int gy = oc >> 3, i = oc & 7;
        int gx = korig >> 3, j = korig & 7;
        float phi = phase[((gy * 144 + gx) * 8 + i) * 8 + j];
        float cc = cosf(phi);
        float ar = MRR_A * MRR_R;
        float num = MRR_A * MRR_A - 2.0f * ar * cc + MRR_R * MRR_R;
        float den = 1.0f - 2.0f * ar * cc + ar * ar;
        float tr = num / den;
        __nv_bfloat16 hi = __float2bfloat16(tr);
        g_w_hi[idx] = hi;
        g_w_lo[idx] = __float2bfloat16(tr - __bfloat162float(hi));
    }
    if (idx < OUT_CH) {
        float inv = gamma[idx] * rsqrtf(rvar[idx] + 1e-5f);
        g_scale[idx] = inv;
        g_bias[idx]  = beta[idx] - rmean[idx] * inv;
    }
}

// ---------------------------------------------------------------------------
// Kernel 2: x NCHW fp32 -> padded NHWC bf16 hi/lo (smem transpose)
// ---------------------------------------------------------------------------
__global__ void __launch_bounds__(256)
xprep_kernel(const float* __restrict__ x) {
    __shared__ float tile[IN_CH][HW + 1];
    const int n = blockIdx.x, h = blockIdx.y;
    const int tid = threadIdx.x;
    const float* xb = x + (size_t)n * IN_CH * HWSQ + h * HW;
    #pragma unroll 4
    for (int i = tid; i < IN_CH * HW; i += 256) {
        int c = i / HW, w = i - c * HW;
        tile[c][w] = xb[(size_t)c * HWSQ + w];
    }
    __syncthreads();
    const size_t obase = (((size_t)n * HWP + h + 1) * HWP + 1) * IN_CH;
    #pragma unroll 4
    for (int i = tid; i < HW * IN_CH; i += 256) {
        int w = i >> 7, c = i & 127;
        float v = tile[c][w];
        __nv_bfloat16 hi = __float2bfloat16(v);
        g_x_hi[obase + (size_t)w * IN_CH + c] = hi;
        g_x_lo[obase + (size_t)w * IN_CH + c] = __float2bfloat16(v - __bfloat162float(hi));
    }
}

// ---------------------------------------------------------------------------
// Kernel 3: implicit-GEMM conv, cp.async 3-stage pipeline, bf16x3 mma.sync
//   512 threads, warp grid 4x4, warp tile 32x32, fragment double-buffering
// ---------------------------------------------------------------------------
__global__ void __launch_bounds__(NTHREADS, 1)
conv_kernel(float* __restrict__ out) {
    extern __shared__ char smem[];
    const uint32_t sb = smem_u32(smem);
    const int tid = threadIdx.x;
    const int wid = tid >> 5;
    const int lid = tid & 31;
    const int p0  = blockIdx.y * MT;   // pixel tile base (grid y)
    const int oc0 = blockIdx.x * NT;   // oc tile base (grid x -> adjacent bids share A)

    const int warpM = wid >> 2;        // 0..3 -> 32-pixel band
    const int warpN = wid & 3;         // 0..3 -> 32-oc band

    if (tid < NT) {
        ((float*)(smem + OFF_SCALE))[tid] = g_scale[oc0 + tid];
        ((float*)(smem + OFF_BIAS))[tid]  = g_bias[oc0 + tid];
    }

    // ---- per-thread load assignment: 4 threads per 128B row, 2 segs each --
    const int lrow = tid >> 2;                 // 0..127 (pixel row & oc row)
    const int segb = (tid & 3) * 2;            // 16B-segment start (of 8)
    const int pg   = p0 + lrow;
    const int nimg = pg / HWSQ;
    const int rem  = pg - nimg * HWSQ;
    const int oh   = rem / HW;
    const int ow   = rem - oh * HW;
    const __nv_bfloat16* xhi_n = g_x_hi + (size_t)nimg * (HWP * HWP * IN_CH);
    const __nv_bfloat16* xlo_n = g_x_lo + (size_t)nimg * (HWP * HWP * IN_CH);
    uint32_t dsts[2];
    #pragma unroll
    for (int j = 0; j < 2; ++j)
        dsts[j] = sw128((uint32_t)(lrow * 128 + (segb + j) * 16));

    auto issue_loads = [&](int kc, int st) {
        const int rs = kc >> 1, half = kc & 1;
        const int r = rs / 3, s = rs - r * 3;
        const size_t aoff = (((size_t)(oh + r) * HWP) + (ow + s)) * IN_CH
                            + half * 64 + segb * 8;
        const __nv_bfloat16* ahi = xhi_n + aoff;
        const __nv_bfloat16* alo = xlo_n + aoff;
        const size_t boff = ((size_t)(oc0 + lrow) * 9 + rs) * 128
                            + half * 64 + segb * 8;
        const __nv_bfloat16* bhi = g_w_hi + boff;
        const __nv_bfloat16* blo = g_w_lo + boff;
        const uint32_t s0 = sb + st * STG_BYTES;
        #pragma unroll
        for (int j = 0; j < 2; ++j) {
            cp16(s0 + SOFF_AHI + dsts[j], ahi + j * 8);
            cp16(s0 + SOFF_ALO + dsts[j], alo + j * 8);
            cp16(s0 + SOFF_BHI + dsts[j], bhi + j * 8);
            cp16(s0 + SOFF_BLO + dsts[j], blo + j * 8);
        }
    };

    float acc[2][4][4];
    #pragma unroll
    for (int f = 0; f < 2; ++f)
        #pragma unroll
        for (int g = 0; g < 4; ++g)
            #pragma unroll
            for (int e = 0; e < 4; ++e) acc[f][g][e] = 0.0f;

    // ldmatrix lane mapping
    const int li = lid >> 3;
    const int lj = lid & 7;
    const int a_row = warpM * 32 + (li & 1) * 8 + lj;
    const int a_kof = (li >> 1) * 8;
    const int b_row = warpN * 32 + (li >> 1) * 8 + lj;
    const int b_kof = (li & 1) * 8;

    // double-buffered fragments (32 regs per buffer)
    uint32_t Ahi[2][2][4], Alo[2][2][4], Bhi[2][4][2], Blo[2][4][2];

    // fragment loader for one ks into buffer bu
    auto load_frags = [&](uint32_t s0, int ks, int bu) {
        #pragma unroll
        for (int f = 0; f < 2; ++f) {
            uint32_t off = sw128((uint32_t)((a_row + f * 16) * 128 +
                                            (ks * 16 + a_kof) * 2));
            ldsm4(Ahi[bu][f], s0 + SOFF_AHI + off);
            ldsm4(Alo[bu][f], s0 + SOFF_ALO + off);
        }
        #pragma unroll
        for (int h = 0; h < 2; ++h) {
            uint32_t off = sw128((uint32_t)((b_row + h * 16) * 128 +
                                            (ks * 16 + b_kof) * 2));
            uint32_t t[4];
            ldsm4(t, s0 + SOFF_BHI + off);
            Bhi[bu][h*2+0][0] = t[0]; Bhi[bu][h*2+0][1] = t[1];
            Bhi[bu][h*2+1][0] = t[2]; Bhi[bu][h*2+1][1] = t[3];
            ldsm4(t, s0 + SOFF_BLO + off);
            Blo[bu][h*2+0][0] = t[0]; Blo[bu][h*2+0][1] = t[1];
            Blo[bu][h*2+1][0] = t[2]; Blo[bu][h*2+1][1] = t[3];
        }
    };

    // ---- pipeline prologue ----
    issue_loads(0, 0); CP_COMMIT();
    issue_loads(1, 1); CP_COMMIT();

    for (int kc = 0; kc < NCHUNK; ++kc) {
        CP_WAIT1();            // stage kc resident
        __syncthreads();       // all warps done reading stage (kc-1)%3

        const uint32_t s0 = sb + (kc % STAGES) * STG_BYTES;

        // critical path first: fragments for ks=0
        load_frags(s0, 0, 0);

        // then issue next-chunk global->shared copies
        const int kn = kc + (STAGES - 1);
        if (kn < NCHUNK) issue_loads(kn, kn % STAGES);
        CP_COMMIT();

        #pragma unroll
        for (int ks = 0; ks < 4; ++ks) {
            const int cur = ks & 1;
            if (ks < 3) load_frags(s0, ks + 1, cur ^ 1);
            #pragma unroll
            for (int f = 0; f < 2; ++f)
                #pragma unroll
                for (int g = 0; g < 4; ++g) {
                    mma16816(acc[f][g], Ahi[cur][f], Bhi[cur][g]);
                    mma16816(acc[f][g], Ahi[cur][f], Blo[cur][g]);
                    mma16816(acc[f][g], Alo[cur][f], Bhi[cur][g]);
                }
        }
    }

    // ---- epilogue: BN + ReLU6 + stores ------------------------------------
    const float* ss = (const float*)(smem + OFF_SCALE);
    const float* bb = (const float*)(smem + OFF_BIAS);

    #pragma unroll
    for (int f = 0; f < 2; ++f) {
        int p1 = p0 + warpM * 32 + f * 16 + (lid >> 2);
        int p2 = p1 + 8;
        int n1 = p1 / HWSQ, r1 = p1 - n1 * HWSQ;
        int n2 = p2 / HWSQ, r2 = p2 - n2 * HWSQ;
        float* o1 = out + (size_t)n1 * OUT_CH * HWSQ + r1;
        float* o2 = out + (size_t)n2 * OUT_CH * HWSQ + r2;
        #pragma unroll
        for (int g = 0; g < 4; ++g) {
            int cl = warpN * 32 + g * 8 + (lid & 3) * 2;
            int ocA = oc0 + cl, ocB = ocA + 1;
            float sA = ss[cl], bA = bb[cl];
            float sB = ss[cl + 1], bB = bb[cl + 1];
            float v0 = fminf(fmaxf(acc[f][g][0] * sA + bA, 0.0f), 6.0f);
            float v1 = fminf(fmaxf(acc[f][g][1] * sB + bB, 0.0f), 6.0f);
            float v2 = fminf(fmaxf(acc[f][g][2] * sA + bA, 0.0f), 6.0f);
            float v3 = fminf(fmaxf(acc[f][g][3] * sB + bB, 0.0f), 6.0f);
            o1[(size_t)ocA * HWSQ] = v0;
            o1[(size_t)ocB * HWSQ] = v1;
            o2[(size_t)ocA * HWSQ] = v2;
            o2[(size_t)ocB * HWSQ] = v3;
        }
    }
}

// ---------------------------------------------------------------------------
// Launch
// ---------------------------------------------------------------------------
extern "C" void kernel_launch(void* const* d_in, const int* in_sizes, int n_in,
                              void* d_out, int out_size) {
    const float* x     = (const float*)d_in[0];
    const float* phase = (const float*)d_in[1];
    const float* gamma = (const float*)d_in[2];
    const float* beta  = (const float*)d_in[3];
    const float* rmean = (const float*)d_in[4];
    const float* rvar  = (const float*)d_in[5];
    float* out = (float*)d_out;

    cudaFuncSetAttribute(conv_kernel,
                         cudaFuncAttributeMaxDynamicSharedMemorySize, SMEM_TOTAL);

    prep_kernel<<<(OUT_CH * KTOT + 255) / 256, 256>>>(phase, gamma, beta, rmean, rvar);
    dim3 xg(64, HW);
    xprep_kernel<<<xg, 256>>>(x);

    dim3 grid(OUT_CH / NT, PIXTOT / MT);   // (2, 1568): oc-major for A-tile L2 reuse
    conv_kernel<<<grid, NTHREADS, SMEM_TOTAL>>>(out);
}

// round 8
// speedup vs baseline: 3.0155x; 1.1773x over previous
#include <cuda_runtime.h>
#include <cuda_bf16.h>
#include <stdint.h>

// ---------------------------------------------------------------------------
// Constants
// ---------------------------------------------------------------------------
#define MRR_A 0.987f
#define MRR_R 0.99f

#define OUT_CH 256
#define IN_CH  128
#define HW     56
#define HWP    58          // padded spatial
#define HWSQ   3136
#define KTOT   1152
#define PIXTOT 200704

#define KC      64
#define NCHUNK  18         // 9 (r,s) positions x 2 channel-halves
#define MT      128
#define NT      128
#define STAGES  3
#define NTHREADS 512       // 16 warps, grid 4x4, warp tile 32x32

// per-stage smem layout (bytes)
#define STG_BYTES 65536
#define SOFF_AHI  0
#define SOFF_ALO  16384
#define SOFF_BHI  32768
#define SOFF_BLO  49152
#define OFF_SCALE (STAGES * STG_BYTES)          // 196608
#define OFF_BIAS  (OFF_SCALE + 512)
#define OFF_MBAR  (OFF_BIAS + 512)              // full[0..2] @ +0,8,16; free[0..2] @ +24,32,40
#define SMEM_TOTAL (OFF_MBAR + 64)

// ---------------------------------------------------------------------------
// Device-global scratch (zero-initialized -> halo stays zero forever)
// ---------------------------------------------------------------------------
__device__ __align__(256) __nv_bfloat16 g_x_hi[64 * HWP * HWP * IN_CH];
__device__ __align__(256) __nv_bfloat16 g_x_lo[64 * HWP * HWP * IN_CH];
__device__ __align__(256) __nv_bfloat16 g_w_hi[OUT_CH * KTOT];   // [oc][rs][c]
__device__ __align__(256) __nv_bfloat16 g_w_lo[OUT_CH * KTOT];
__device__ float g_scale[OUT_CH];
__device__ float g_bias[OUT_CH];

// ---------------------------------------------------------------------------
// Helpers
// ---------------------------------------------------------------------------
__device__ __forceinline__ uint32_t smem_u32(const void* p) {
    uint32_t a;
    asm("{ .reg .u64 t; cvta.to.shared.u64 t, %1; cvt.u32.u64 %0, t; }" : "=r"(a) : "l"(p));
    return a;
}
__device__ __forceinline__ uint32_t sw128(uint32_t off) {
    return off ^ ((off >> 3) & 0x70);
}
__device__ __forceinline__ void cp16(uint32_t dst, const __nv_bfloat16* src) {
    asm volatile("cp.async.cg.shared.global [%0], [%1], 16;"
                 :: "r"(dst), "l"(__cvta_generic_to_global(src)));
}

#define MBAR_INIT(a, c) \
    asm volatile("mbarrier.init.shared.b64 [%0], %1;" :: "r"(a), "r"(c) : "memory")
#define CP_MBAR_ARRIVE(a) \
    asm volatile("cp.async.mbarrier.arrive.noinc.shared.b64 [%0];" :: "r"(a) : "memory")
#define MBAR_ARRIVE(a) \
    asm volatile("mbarrier.arrive.shared.b64 _, [%0];" :: "r"(a) : "memory")

#define MBAR_WAIT(mbar, parity) do {                                              \
    uint32_t _m = (uint32_t)(mbar);                                               \
    uint32_t _p = (uint32_t)(parity);                                             \
    uint32_t _done;                                                               \
    asm volatile(                                                                 \
        "{\n\t.reg .pred p;\n\t"                                                  \
        "mbarrier.try_wait.parity.acquire.cta.shared::cta.b64 p, [%1], %2;\n\t"   \
        "selp.b32 %0, 1, 0, p;\n\t}"                                              \
        : "=r"(_done) : "r"(_m), "r"(_p) : "memory");                             \
    if (!_done) {                                                                 \
        asm volatile(                                                             \
            "{\n\t.reg .pred P1;\n\t"                                             \
            "WAIT_LOOP_%=:\n\t"                                                   \
            "mbarrier.try_wait.parity.acquire.cta.shared::cta.b64 P1, [%0], %1, 0x989680;\n\t" \
            "@P1 bra.uni WAIT_DONE_%=;\n\t"                                       \
            "bra.uni WAIT_LOOP_%=;\n\t"                                           \
            "WAIT_DONE_%=:\n\t}"                                                  \
            :: "r"(_m), "r"(_p) : "memory");                                      \
    }                                                                             \
} while (0)

__device__ __forceinline__ void ldsm4(uint32_t* r, uint32_t addr) {
    asm volatile("ldmatrix.sync.aligned.m8n8.x4.shared.b16 {%0,%1,%2,%3}, [%4];"
                 : "=r"(r[0]), "=r"(r[1]), "=r"(r[2]), "=r"(r[3]) : "r"(addr));
}
__device__ __forceinline__ void mma16816(float* d, const uint32_t* a, const uint32_t* b) {
    asm volatile(
        "mma.sync.aligned.m16n8k16.row.col.f32.bf16.bf16.f32 "
        "{%0,%1,%2,%3}, {%4,%5,%6,%7}, {%8,%9}, {%0,%1,%2,%3};"
        : "+f"(d[0]), "+f"(d[1]), "+f"(d[2]), "+f"(d[3])
        : "r"(a[0]), "r"(a[1]), "r"(a[2]), "r"(a[3]), "r"(b[0]), "r"(b[1]));
}

// ---------------------------------------------------------------------------
// Kernel 1: weights — MRR phase -> bf16 hi/lo in [oc][rs][c] order + BN fold
// ---------------------------------------------------------------------------
__global__ void prep_kernel(const float* __restrict__ phase,
                            const float* __restrict__ gamma,
                            const float* __restrict__ beta,
                            const float* __restrict__ rmean,
                            const float* __restrict__ rvar) {
    int idx = blockIdx.x * 256 + threadIdx.x;
    if (idx < OUT_CH * KTOT) {
        int oc  = idx / KTOT;
        int kp  = idx - oc * KTOT;     // rs*128 + c
        int rs  = kp >> 7;
        int c   = kp & 127;
        int korig = c * 9 + rs;        // original (c,r,s) K order used by the blocks
        int gy = oc >> 3, i = oc & 7;
        int gx = korig >> 3, j = korig & 7;
        float phi = phase[((gy * 144 + gx) * 8 + i) * 8 + j];
        float cc = cosf(phi);
        float ar = MRR_A * MRR_R;
        float num = MRR_A * MRR_A - 2.0f * ar * cc + MRR_R * MRR_R;
        float den = 1.0f - 2.0f * ar * cc + ar * ar;
        float tr = num / den;
        __nv_bfloat16 hi = __float2bfloat16(tr);
        g_w_hi[idx] = hi;
        g_w_lo[idx] = __float2bfloat16(tr - __bfloat162float(hi));
    }
    if (idx < OUT_CH) {
        float inv = gamma[idx] * rsqrtf(rvar[idx] + 1e-5f);
        g_scale[idx] = inv;
        g_bias[idx]  = beta[idx] - rmean[idx] * inv;
    }
}

// ---------------------------------------------------------------------------
// Kernel 2: x NCHW fp32 -> padded NHWC bf16 hi/lo (smem transpose)
// ---------------------------------------------------------------------------
__global__ void __launch_bounds__(256)
xprep_kernel(const float* __restrict__ x) {
    __shared__ float tile[IN_CH][HW + 1];
    const int n = blockIdx.x, h = blockIdx.y;
    const int tid = threadIdx.x;
    const float* xb = x + (size_t)n * IN_CH * HWSQ + h * HW;
    #pragma unroll 4
    for (int i = tid; i < IN_CH * HW; i += 256) {
        int c = i / HW, w = i - c * HW;
        tile[c][w] = xb[(size_t)c * HWSQ + w];
    }
    __syncthreads();
    const size_t obase = (((size_t)n * HWP + h + 1) * HWP + 1) * IN_CH;
    #pragma unroll 4
    for (int i = tid; i < HW * IN_CH; i += 256) {
        int w = i >> 7, c = i & 127;
        float v = tile[c][w];
        __nv_bfloat16 hi = __float2bfloat16(v);
        g_x_hi[obase + (size_t)w * IN_CH + c] = hi;
        g_x_lo[obase + (size_t)w * IN_CH + c] = __float2bfloat16(v - __bfloat162float(hi));
    }
}

// ---------------------------------------------------------------------------
// Kernel 3: implicit-GEMM conv, mbarrier-decoupled 3-stage pipeline, bf16x3
//   512 threads, warp grid 4x4, warp tile 32x32, fragment double-buffering
// ---------------------------------------------------------------------------
__global__ void __launch_bounds__(NTHREADS, 1)
conv_kernel(float* __restrict__ out) {
    extern __shared__ char smem[];
    const uint32_t sb = smem_u32(smem);
    const uint32_t mb = sb + OFF_MBAR;
    const int tid = threadIdx.x;
    const int wid = tid >> 5;
    const int lid = tid & 31;
    const int p0  = blockIdx.y * MT;   // pixel tile base
    const int oc0 = blockIdx.x * NT;   // oc tile base (adjacent bids share A in L2)

    const int warpM = wid >> 2;        // 0..3 -> 32-pixel band
    const int warpN = wid & 3;         // 0..3 -> 32-oc band

    if (tid == 0) {
        #pragma unroll
        for (int s = 0; s < STAGES; ++s) {
            MBAR_INIT(mb + s * 8, NTHREADS);        // full[s]
            MBAR_INIT(mb + 24 + s * 8, NTHREADS);   // free[s]
        }
    }
    if (tid < NT) {
        ((float*)(smem + OFF_SCALE))[tid] = g_scale[oc0 + tid];
        ((float*)(smem + OFF_BIAS))[tid]  = g_bias[oc0 + tid];
    }
    __syncthreads();   // mbarrier init + scale/bias visible; only CTA-wide barrier

    // ---- per-thread load assignment: 4 threads per 128B row, 2 segs each --
    const int lrow = tid >> 2;                 // 0..127 (pixel row & oc row)
    const int segb = (tid & 3) * 2;            // 16B-segment start (of 8)
    const int pg   = p0 + lrow;
    const int nimg = pg / HWSQ;
    const int rem  = pg - nimg * HWSQ;
    const int oh   = rem / HW;
    const int ow   = rem - oh * HW;
    const __nv_bfloat16* xhi_n = g_x_hi + (size_t)nimg * (HWP * HWP * IN_CH);
    const __nv_bfloat16* xlo_n = g_x_lo + (size_t)nimg * (HWP * HWP * IN_CH);
    uint32_t dsts[2];
    #pragma unroll
    for (int j = 0; j < 2; ++j)
        dsts[j] = sw128((uint32_t)(lrow * 128 + (segb + j) * 16));

    auto issue_loads = [&](int kc, int st) {
        const int rs = kc >> 1, half = kc & 1;
        const int r = rs / 3, s = rs - r * 3;
        const size_t aoff = (((size_t)(oh + r) * HWP) + (ow + s)) * IN_CH
                            + half * 64 + segb * 8;
        const __nv_bfloat16* ahi = xhi_n + aoff;
        const __nv_bfloat16* alo = xlo_n + aoff;
        const size_t boff = ((size_t)(oc0 + lrow) * 9 + rs) * 128
                            + half * 64 + segb * 8;
        const __nv_bfloat16* bhi = g_w_hi + boff;
        const __nv_bfloat16* blo = g_w_lo + boff;
        const uint32_t s0 = sb + st * STG_BYTES;
        #pragma unroll
        for (int j = 0; j < 2; ++j) {
            cp16(s0 + SOFF_AHI + dsts[j], ahi + j * 8);
            cp16(s0 + SOFF_ALO + dsts[j], alo + j * 8);
            cp16(s0 + SOFF_BHI + dsts[j], bhi + j * 8);
            cp16(s0 + SOFF_BLO + dsts[j], blo + j * 8);
        }
    };

    float acc[2][4][4];
    #pragma unroll
    for (int f = 0; f < 2; ++f)
        #pragma unroll
        for (int g = 0; g < 4; ++g)
            #pragma unroll
            for (int e = 0; e < 4; ++e) acc[f][g][e] = 0.0f;

    // ldmatrix lane mapping
    const int li = lid >> 3;
    const int lj = lid & 7;
    const int a_row = warpM * 32 + (li & 1) * 8 + lj;
    const int a_kof = (li >> 1) * 8;
    const int b_row = warpN * 32 + (li >> 1) * 8 + lj;
    const int b_kof = (li & 1) * 8;

    // double-buffered fragments (32 regs per buffer)
    uint32_t Ahi[2][2][4], Alo[2][2][4], Bhi[2][4][2], Blo[2][4][2];

    auto load_frags = [&](uint32_t s0, int ks, int bu) {
        #pragma unroll
        for (int f = 0; f < 2; ++f) {
            uint32_t off = sw128((uint32_t)((a_row + f * 16) * 128 +
                                            (ks * 16 + a_kof) * 2));
            ldsm4(Ahi[bu][f], s0 + SOFF_AHI + off);
            ldsm4(Alo[bu][f], s0 + SOFF_ALO + off);
        }
        #pragma unroll
        for (int h = 0; h < 2; ++h) {
            uint32_t off = sw128((uint32_t)((b_row + h * 16) * 128 +
                                            (ks * 16 + b_kof) * 2));
            uint32_t t[4];
            ldsm4(t, s0 + SOFF_BHI + off);
            Bhi[bu][h*2+0][0] = t[0]; Bhi[bu][h*2+0][1] = t[1];
            Bhi[bu][h*2+1][0] = t[2]; Bhi[bu][h*2+1][1] = t[3];
            ldsm4(t, s0 + SOFF_BLO + off);
            Blo[bu][h*2+0][0] = t[0]; Blo[bu][h*2+0][1] = t[1];
            Blo[bu][h*2+1][0] = t[2]; Blo[bu][h*2+1][1] = t[3];
        }
    };

    // ---- pipeline prologue: fill stages 0 and 1 ----
    issue_loads(0, 0); CP_MBAR_ARRIVE(mb + 0);
    issue_loads(1, 1); CP_MBAR_ARRIVE(mb + 8);

    for (int kc = 0; kc < NCHUNK; ++kc) {
        const int rnd = kc / 3;
        const int s   = kc - rnd * 3;
        MBAR_WAIT(mb + s * 8, rnd & 1);        // stage kc data (all threads') ready

        const uint32_t s0 = sb + s * STG_BYTES;
        load_frags(s0, 0, 0);

        #pragma unroll
        for (int ks = 0; ks < 4; ++ks) {
            const int cur = ks & 1;
            if (ks < 3) load_frags(s0, ks + 1, cur ^ 1);
            #pragma unroll
            for (int f = 0; f < 2; ++f)
                #pragma unroll
                for (int g = 0; g < 4; ++g) {
                    mma16816(acc[f][g], Ahi[cur][f], Bhi[cur][g]);
                    mma16816(acc[f][g], Ahi[cur][f], Blo[cur][g]);
                    mma16816(acc[f][g], Alo[cur][f], Bhi[cur][g]);
                }
        }

        MBAR_ARRIVE(mb + 24 + s * 8);          // done reading stage s this round

        const int kn = kc + 2;
        if (kn < NCHUNK) {
            const int rn = kn / 3;
            const int sn = kn - rn * 3;
            if (kn >= STAGES)                  // stage sn last read in chunk kn-3
                MBAR_WAIT(mb + 24 + sn * 8, (rn - 1) & 1);
            issue_loads(kn, sn);
            CP_MBAR_ARRIVE(mb + sn * 8);
        }
    }

    // ---- epilogue: BN + ReLU6 + stores ------------------------------------
    const float* ss = (const float*)(smem + OFF_SCALE);
    const float* bb = (const float*)(smem + OFF_BIAS);

    #pragma unroll
    for (int f = 0; f < 2; ++f) {
        int p1 = p0 + warpM * 32 + f * 16 + (lid >> 2);
        int p2 = p1 + 8;
        int n1 = p1 / HWSQ, r1 = p1 - n1 * HWSQ;
        int n2 = p2 / HWSQ, r2 = p2 - n2 * HWSQ;
        float* o1 = out + (size_t)n1 * OUT_CH * HWSQ + r1;
        float* o2 = out + (size_t)n2 * OUT_CH * HWSQ + r2;
        #pragma unroll
        for (int g = 0; g < 4; ++g) {
            int cl = warpN * 32 + g * 8 + (lid & 3) * 2;
            int ocA = oc0 + cl, ocB = ocA + 1;
            float sA = ss[cl], bA = bb[cl];
            float sB = ss[cl + 1], bB = bb[cl + 1];
            float v0 = fminf(fmaxf(acc[f][g][0] * sA + bA, 0.0f), 6.0f);
            float v1 = fminf(fmaxf(acc[f][g][1] * sB + bB, 0.0f), 6.0f);
            float v2 = fminf(fmaxf(acc[f][g][2] * sA + bA, 0.0f), 6.0f);
            float v3 = fminf(fmaxf(acc[f][g][3] * sB + bB, 0.0f), 6.0f);
            o1[(size_t)ocA * HWSQ] = v0;
            o1[(size_t)ocB * HWSQ] = v1;
            o2[(size_t)ocA * HWSQ] = v2;
            o2[(size_t)ocB * HWSQ] = v3;
        }
    }
}

// ---------------------------------------------------------------------------
// Launch
// ---------------------------------------------------------------------------
extern "C" void kernel_launch(void* const* d_in, const int* in_sizes, int n_in,
                              void* d_out, int out_size) {
    const float* x     = (const float*)d_in[0];
    const float* phase = (const float*)d_in[1];
    const float* gamma = (const float*)d_in[2];
    const float* beta  = (const float*)d_in[3];
    const float* rmean = (const float*)d_in[4];
    const float* rvar  = (const float*)d_in[5];
    float* out = (float*)d_out;

    cudaFuncSetAttribute(conv_kernel,
                         cudaFuncAttributeMaxDynamicSharedMemorySize, SMEM_TOTAL);

    prep_kernel<<<(OUT_CH * KTOT + 255) / 256, 256>>>(phase, gamma, beta, rmean, rvar);
    dim3 xg(64, HW);
    xprep_kernel<<<xg, 256>>>(x);

    dim3 grid(OUT_CH / NT, PIXTOT / MT);   // (2, 1568): oc-major for A-tile L2 reuse
    conv_kernel<<<grid, NTHREADS, SMEM_TOTAL>>>(out);
}

// round 9
// speedup vs baseline: 3.2200x; 1.0678x over previous
#include <cuda_runtime.h>
#include <cuda_bf16.h>
#include <stdint.h>

// ---------------------------------------------------------------------------
// Constants
// ---------------------------------------------------------------------------
#define MRR_A 0.987f
#define MRR_R 0.99f

#define OUT_CH 256
#define IN_CH  128
#define HW     56
#define HWP    58          // padded spatial
#define HWSQ   3136
#define KTOT   1152
#define PIXTOT 200704

#define KC      64
#define NCHUNK  18         // 9 (r,s) positions x 2 channel-halves
#define MT      128
#define NT      128
#define STAGES  3
#define NTHREADS 512       // 16 warps, grid 4x4, warp tile 32x32

// per-stage smem layout (bytes)
#define STG_BYTES 65536
#define SOFF_AHI  0
#define SOFF_ALO  16384
#define SOFF_BHI  32768
#define SOFF_BLO  49152
#define OFF_SCALE (STAGES * STG_BYTES)          // 196608
#define OFF_BIAS  (OFF_SCALE + 512)
#define OFF_MBAR  (OFF_BIAS + 512)              // full[0..2] @ +0,8,16; free[0..2] @ +24,32,40
#define SMEM_TOTAL (OFF_MBAR + 64)

// ---------------------------------------------------------------------------
// Device-global scratch (zero-initialized -> halo stays zero forever)
// ---------------------------------------------------------------------------
__device__ __align__(256) __nv_bfloat16 g_x_hi[64 * HWP * HWP * IN_CH];
__device__ __align__(256) __nv_bfloat16 g_x_lo[64 * HWP * HWP * IN_CH];
__device__ __align__(256) __nv_bfloat16 g_w_hi[OUT_CH * KTOT];   // [oc][rs][c]
__device__ __align__(256) __nv_bfloat16 g_w_lo[OUT_CH * KTOT];
__device__ float g_scale[OUT_CH];
__device__ float g_bias[OUT_CH];

// ---------------------------------------------------------------------------
// Helpers
// ---------------------------------------------------------------------------
__device__ __forceinline__ uint32_t smem_u32(const void* p) {
    uint32_t a;
    asm("{ .reg .u64 t; cvta.to.shared.u64 t, %1; cvt.u32.u64 %0, t; }" : "=r"(a) : "l"(p));
    return a;
}
__device__ __forceinline__ uint32_t sw128(uint32_t off) {
    return off ^ ((off >> 3) & 0x70);
}
__device__ __forceinline__ void cp16(uint32_t dst, const __nv_bfloat16* src) {
    asm volatile("cp.async.cg.shared.global [%0], [%1], 16;"
                 :: "r"(dst), "l"(__cvta_generic_to_global(src)));
}

#define MBAR_INIT(a, c) \
    asm volatile("mbarrier.init.shared.b64 [%0], %1;" :: "r"(a), "r"(c) : "memory")
#define CP_MBAR_ARRIVE(a) \
    asm volatile("cp.async.mbarrier.arrive.noinc.shared.b64 [%0];" :: "r"(a) : "memory")
#define MBAR_ARRIVE(a) \
    asm volatile("mbarrier.arrive.shared.b64 _, [%0];" :: "r"(a) : "memory")

#define MBAR_WAIT(mbar, parity) do {                                              \
    uint32_t _m = (uint32_t)(mbar);                                               \
    uint32_t _p = (uint32_t)(parity);                                             \
    uint32_t _done;                                                               \
    asm volatile(                                                                 \
        "{\n\t.reg .pred p;\n\t"                                                  \
        "mbarrier.try_wait.parity.acquire.cta.shared::cta.b64 p, [%1], %2;\n\t"   \
        "selp.b32 %0, 1, 0, p;\n\t}"                                              \
        : "=r"(_done) : "r"(_m), "r"(_p) : "memory");                             \
    if (!_done) {                                                                 \
        asm volatile(                                                             \
            "{\n\t.reg .pred P1;\n\t"                                             \
            "WAIT_LOOP_%=:\n\t"                                                   \
            "mbarrier.try_wait.parity.acquire.cta.shared::cta.b64 P1, [%0], %1, 0x989680;\n\t" \
            "@P1 bra.uni WAIT_DONE_%=;\n\t"                                       \
            "bra.uni WAIT_LOOP_%=;\n\t"                                           \
            "WAIT_DONE_%=:\n\t}"                                                  \
            :: "r"(_m), "r"(_p) : "memory");                                      \
    }                                                                             \
} while (0)

__device__ __forceinline__ void ldsm4(uint32_t* r, uint32_t addr) {
    asm volatile("ldmatrix.sync.aligned.m8n8.x4.shared.b16 {%0,%1,%2,%3}, [%4];"
                 : "=r"(r[0]), "=r"(r[1]), "=r"(r[2]), "=r"(r[3]) : "r"(addr));
}
__device__ __forceinline__ void mma16816(float* d, const uint32_t* a, const uint32_t* b) {
    asm volatile(
        "mma.sync.aligned.m16n8k16.row.col.f32.bf16.bf16.f32 "
        "{%0,%1,%2,%3}, {%4,%5,%6,%7}, {%8,%9}, {%0,%1,%2,%3};"
        : "+f"(d[0]), "+f"(d[1]), "+f"(d[2]), "+f"(d[3])
        : "r"(a[0]), "r"(a[1]), "r"(a[2]), "r"(a[3]), "r"(b[0]), "r"(b[1]));
}

// ---------------------------------------------------------------------------
// Kernel 1: weights — MRR phase -> bf16 hi/lo in [oc][rs][c] order + BN fold
// ---------------------------------------------------------------------------
__global__ void prep_kernel(const float* __restrict__ phase,
                            const float* __restrict__ gamma,
                            const float* __restrict__ beta,
                            const float* __restrict__ rmean,
                            const float* __restrict__ rvar) {
    int idx = blockIdx.x * 256 + threadIdx.x;
    if (idx < OUT_CH * KTOT) {
        int oc  = idx / KTOT;
        int kp  = idx - oc * KTOT;     // rs*128 + c
        int rs  = kp >> 7;
        int c   = kp & 127;
        int korig = c * 9 + rs;        // original (c,r,s) K order used by the blocks
        int gy = oc >> 3, i = oc & 7;
        int gx = korig >> 3, j = korig & 7;
        float phi = phase[((gy * 144 + gx) * 8 + i) * 8 + j];
        float cc = cosf(phi);
        float ar = MRR_A * MRR_R;
        float num = MRR_A * MRR_A - 2.0f * ar * cc + MRR_R * MRR_R;
        float den = 1.0f - 2.0f * ar * cc + ar * ar;
        float tr = num / den;
        __nv_bfloat16 hi = __float2bfloat16(tr);
        g_w_hi[idx] = hi;
        g_w_lo[idx] = __float2bfloat16(tr - __bfloat162float(hi));
    }
    if (idx < OUT_CH) {
        float inv = gamma[idx] * rsqrtf(rvar[idx] + 1e-5f);
        g_scale[idx] = inv;
        g_bias[idx]  = beta[idx] - rmean[idx] * inv;
    }
}

// ---------------------------------------------------------------------------
// Kernel 2: x NCHW fp32 -> padded NHWC bf16 hi/lo (smem transpose)
// ---------------------------------------------------------------------------
__global__ void __launch_bounds__(256)
xprep_kernel(const float* __restrict__ x) {
    __shared__ float tile[IN_CH][HW + 1];
    const int n = blockIdx.x, h = blockIdx.y;
    const int tid = threadIdx.x;
    const float* xb = x + (size_t)n * IN_CH * HWSQ + h * HW;
    #pragma unroll 4
    for (int i = tid; i < IN_CH * HW; i += 256) {
        int c = i / HW, w = i - c * HW;
        tile[c][w] = xb[(size_t)c * HWSQ + w];
    }
    __syncthreads();
    const size_t obase = (((size_t)n * HWP + h + 1) * HWP + 1) * IN_CH;
    #pragma unroll 4
    for (int i = tid; i < HW * IN_CH; i += 256) {
        int w = i >> 7, c = i & 127;
        float v = tile[c][w];
        __nv_bfloat16 hi = __float2bfloat16(v);
        g_x_hi[obase + (size_t)w * IN_CH + c] = hi;
        g_x_lo[obase + (size_t)w * IN_CH + c] = __float2bfloat16(v - __bfloat162float(hi));
    }
}

// ---------------------------------------------------------------------------
// Kernel 3: implicit-GEMM conv, mbarrier 3-stage pipeline, bf16x3 mma.sync
//   512 threads, warp grid 4x4, warp tile 32x32, cross-chunk fragment pipeline
// ---------------------------------------------------------------------------
__global__ void __launch_bounds__(NTHREADS, 1)
conv_kernel(float* __restrict__ out) {
    extern __shared__ char smem[];
    const uint32_t sb = smem_u32(smem);
    const uint32_t mb = sb + OFF_MBAR;
    const int tid = threadIdx.x;
    const int wid = tid >> 5;
    const int lid = tid & 31;
    const int p0  = blockIdx.y * MT;   // pixel tile base
    const int oc0 = blockIdx.x * NT;   // oc tile base (adjacent bids share A in L2)

    const int warpM = wid >> 2;        // 0..3 -> 32-pixel band
    const int warpN = wid & 3;         // 0..3 -> 32-oc band

    if (tid == 0) {
        #pragma unroll
        for (int s = 0; s < STAGES; ++s) {
            MBAR_INIT(mb + s * 8, NTHREADS);        // full[s]
            MBAR_INIT(mb + 24 + s * 8, NTHREADS);   // free[s]
        }
    }
    if (tid < NT) {
        ((float*)(smem + OFF_SCALE))[tid] = g_scale[oc0 + tid];
        ((float*)(smem + OFF_BIAS))[tid]  = g_bias[oc0 + tid];
    }
    __syncthreads();   // mbarrier init + scale/bias visible; only CTA-wide barrier

    // ---- per-thread load assignment: 4 threads per 128B row, 2 segs each --
    const int lrow = tid >> 2;                 // 0..127 (pixel row & oc row)
    const int segb = (tid & 3) * 2;            // 16B-segment start (of 8)
    const int pg   = p0 + lrow;
    const int nimg = pg / HWSQ;
    const int rem  = pg - nimg * HWSQ;
    const int oh   = rem / HW;
    const int ow   = rem - oh * HW;
    const __nv_bfloat16* xhi_n = g_x_hi + (size_t)nimg * (HWP * HWP * IN_CH);
    const __nv_bfloat16* xlo_n = g_x_lo + (size_t)nimg * (HWP * HWP * IN_CH);
    uint32_t dsts[2];
    #pragma unroll
    for (int j = 0; j < 2; ++j)
        dsts[j] = sw128((uint32_t)(lrow * 128 + (segb + j) * 16));

    auto issue_loads = [&](int kc, int st) {
        const int rs = kc >> 1, half = kc & 1;
        const int r = rs / 3, s = rs - r * 3;
        const size_t aoff = (((size_t)(oh + r) * HWP) + (ow + s)) * IN_CH
                            + half * 64 + segb * 8;
        const __nv_bfloat16* ahi = xhi_n + aoff;
        const __nv_bfloat16* alo = xlo_n + aoff;
        const size_t boff = ((size_t)(oc0 + lrow) * 9 + rs) * 128
                            + half * 64 + segb * 8;
        const __nv_bfloat16* bhi = g_w_hi + boff;
        const __nv_bfloat16* blo = g_w_lo + boff;
        const uint32_t s0 = sb + st * STG_BYTES;
        #pragma unroll
        for (int j = 0; j < 2; ++j) {
            cp16(s0 + SOFF_AHI + dsts[j], ahi + j * 8);
            cp16(s0 + SOFF_ALO + dsts[j], alo + j * 8);
            cp16(s0 + SOFF_BHI + dsts[j], bhi + j * 8);
            cp16(s0 + SOFF_BLO + dsts[j], blo + j * 8);
        }
    };

    float acc[2][4][4];
    #pragma unroll
    for (int f = 0; f < 2; ++f)
        #pragma unroll
        for (int g = 0; g < 4; ++g)
            #pragma unroll
            for (int e = 0; e < 4; ++e) acc[f][g][e] = 0.0f;

    // ldmatrix lane mapping
    const int li = lid >> 3;
    const int lj = lid & 7;
    const int a_row = warpM * 32 + (li & 1) * 8 + lj;
    const int a_kof = (li >> 1) * 8;
    const int b_row = warpN * 32 + (li >> 1) * 8 + lj;
    const int b_kof = (li & 1) * 8;

    // double-buffered fragments (alternating across the whole K loop)
    uint32_t Ahi[2][2][4], Alo[2][2][4], Bhi[2][4][2], Blo[2][4][2];

    auto load_frags = [&](uint32_t s0, int ks, int bu) {
        #pragma unroll
        for (int f = 0; f < 2; ++f) {
            uint32_t off = sw128((uint32_t)((a_row + f * 16) * 128 +
                                            (ks * 16 + a_kof) * 2));
            ldsm4(Ahi[bu][f], s0 + SOFF_AHI + off);
            ldsm4(Alo[bu][f], s0 + SOFF_ALO + off);
        }
        #pragma unroll
        for (int h = 0; h < 2; ++h) {
            uint32_t off = sw128((uint32_t)((b_row + h * 16) * 128 +
                                            (ks * 16 + b_kof) * 2));
            uint32_t t[4];
            ldsm4(t, s0 + SOFF_BHI + off);
            Bhi[bu][h*2+0][0] = t[0]; Bhi[bu][h*2+0][1] = t[1];
            Bhi[bu][h*2+1][0] = t[2]; Bhi[bu][h*2+1][1] = t[3];
            ldsm4(t, s0 + SOFF_BLO + off);
            Blo[bu][h*2+0][0] = t[0]; Blo[bu][h*2+0][1] = t[1];
            Blo[bu][h*2+1][0] = t[2]; Blo[bu][h*2+1][1] = t[3];
        }
    };

    // ---- pipeline prologue: fill stages 0 and 1; preload chunk0 ks0 frags --
    issue_loads(0, 0); CP_MBAR_ARRIVE(mb + 0);
    issue_loads(1, 1); CP_MBAR_ARRIVE(mb + 8);
    MBAR_WAIT(mb + 0, 0);
    load_frags(sb, 0, 0);

    for (int kc = 0; kc < NCHUNK; ++kc) {
        const int rnd = kc / 3;
        const int s   = kc - rnd * 3;
        const uint32_t s0 = sb + s * STG_BYTES;

        // ks = 0..2: prefetch next ks of this stage, then MMA
        #pragma unroll
        for (int ks = 0; ks < 3; ++ks) {
            const int cur = ks & 1;
            load_frags(s0, ks + 1, cur ^ 1);
            #pragma unroll
            for (int f = 0; f < 2; ++f)
                #pragma unroll
                for (int g = 0; g < 4; ++g) {
                    mma16816(acc[f][g], Ahi[cur][f], Bhi[cur][g]);
                    mma16816(acc[f][g], Ahi[cur][f], Blo[cur][g]);
                    mma16816(acc[f][g], Alo[cur][f], Bhi[cur][g]);
                }
        }

        // ks = 3: cross-chunk prefetch (next chunk's ks0 from next stage)
        {
            const int cur = 1;  // ks=3 buffer
            if (kc + 1 < NCHUNK) {
                const int rn1 = (kc + 1) / 3;
                const int sn1 = (kc + 1) - rn1 * 3;
                MBAR_WAIT(mb + sn1 * 8, rn1 & 1);            // usually already fired
                load_frags(sb + sn1 * STG_BYTES, 0, 0);      // next chunk ks0 -> buf 0
            }
            MBAR_ARRIVE(mb + 24 + s * 8);                    // done reading stage s
            #pragma unroll
            for (int f = 0; f < 2; ++f)
                #pragma unroll
                for (int g = 0; g < 4; ++g) {
                    mma16816(acc[f][g], Ahi[cur][f], Bhi[cur][g]);
                    mma16816(acc[f][g], Ahi[cur][f], Blo[cur][g]);
                    mma16816(acc[f][g], Alo[cur][f], Bhi[cur][g]);
                }
        }

        // refill: stage (kc+2)%3 with chunk kc+2
        const int kn = kc + 2;
        if (kn < NCHUNK) {
            const int rn = kn / 3;
            const int sn = kn - rn * 3;
            if (kn >= STAGES)                  // stage sn last read in chunk kn-3
                MBAR_WAIT(mb + 24 + sn * 8, (rn - 1) & 1);
            issue_loads(kn, sn);
            CP_MBAR_ARRIVE(mb + sn * 8);
        }
    }

    // ---- epilogue: BN + ReLU6 + stores ------------------------------------
    const float* ss = (const float*)(smem + OFF_SCALE);
    const float* bb = (const float*)(smem + OFF_BIAS);

    #pragma unroll
    for (int f = 0; f < 2; ++f) {
        int p1 = p0 + warpM * 32 + f * 16 + (lid >> 2);
        int p2 = p1 + 8;
        int n1 = p1 / HWSQ, r1 = p1 - n1 * HWSQ;
        int n2 = p2 / HWSQ, r2 = p2 - n2 * HWSQ;
        float* o1 = out + (size_t)n1 * OUT_CH * HWSQ + r1;
        float* o2 = out + (size_t)n2 * OUT_CH * HWSQ + r2;
        #pragma unroll
        for (int g = 0; g < 4; ++g) {
            int cl = warpN * 32 + g * 8 + (lid & 3) * 2;
            int ocA = oc0 + cl, ocB = ocA + 1;
            float sA = ss[cl], bA = bb[cl];
            float sB = ss[cl + 1], bB = bb[cl + 1];
            float v0 = fminf(fmaxf(acc[f][g][0] * sA + bA, 0.0f), 6.0f);
            float v1 = fminf(fmaxf(acc[f][g][1] * sB + bB, 0.0f), 6.0f);
            float v2 = fminf(fmaxf(acc[f][g][2] * sA + bA, 0.0f), 6.0f);
            float v3 = fminf(fmaxf(acc[f][g][3] * sB + bB, 0.0f), 6.0f);
            o1[(size_t)ocA * HWSQ] = v0;
            o1[(size_t)ocB * HWSQ] = v1;
            o2[(size_t)ocA * HWSQ] = v2;
            o2[(size_t)ocB * HWSQ] = v3;
        }
    }
}

// ---------------------------------------------------------------------------
// Launch
// ---------------------------------------------------------------------------
extern "C" void kernel_launch(void* const* d_in, const int* in_sizes, int n_in,
                              void* d_out, int out_size) {
    const float* x     = (const float*)d_in[0];
    const float* phase = (const float*)d_in[1];
    const float* gamma = (const float*)d_in[2];
    const float* beta  = (const float*)d_in[3];
    const float* rmean = (const float*)d_in[4];
    const float* rvar  = (const float*)d_in[5];
    float* out = (float*)d_out;

    cudaFuncSetAttribute(conv_kernel,
                         cudaFuncAttributeMaxDynamicSharedMemorySize, SMEM_TOTAL);

    prep_kernel<<<(OUT_CH * KTOT + 255) / 256, 256>>>(phase, gamma, beta, rmean, rvar);
    dim3 xg(64, HW);
    xprep_kernel<<<xg, 256>>>(x);

    dim3 grid(OUT_CH / NT, PIXTOT / MT);   // (2, 1568): oc-major for A-tile L2 reuse
    conv_kernel<<<grid, NTHREADS, SMEM_TOTAL>>>(out);
}

// round 10
// speedup vs baseline: 3.2290x; 1.0028x over previous
#include <cuda_runtime.h>
#include <cuda_bf16.h>
#include <stdint.h>

// ---------------------------------------------------------------------------
// Constants
// ---------------------------------------------------------------------------
#define MRR_A 0.987f
#define MRR_R 0.99f

#define OUT_CH 256
#define IN_CH  128
#define HW     56
#define HWP    58          // padded spatial
#define HWSQ   3136
#define KTOT   1152
#define PIXTOT 200704

#define KC      64
#define NCHUNK  18         // 9 (r,s) positions x 2 channel-halves
#define MT      128
#define NT      128
#define STAGES  3
#define NTHREADS 512       // 16 warps, grid 4x4, warp tile 32x32
#define NWARPS  16

// per-stage smem layout (bytes)
#define STG_BYTES 65536
#define SOFF_AHI  0
#define SOFF_ALO  16384
#define SOFF_BHI  32768
#define SOFF_BLO  49152
#define OFF_SCALE (STAGES * STG_BYTES)          // 196608
#define OFF_BIAS  (OFF_SCALE + 512)
#define OFF_MBAR  (OFF_BIAS + 512)              // full[0..2] @ +0,8,16; free[0..2] @ +24,32,40
#define SMEM_TOTAL (OFF_MBAR + 64)

// ---------------------------------------------------------------------------
// Device-global scratch (zero-initialized -> halo stays zero forever)
// ---------------------------------------------------------------------------
__device__ __align__(256) __nv_bfloat16 g_x_hi[64 * HWP * HWP * IN_CH];
__device__ __align__(256) __nv_bfloat16 g_x_lo[64 * HWP * HWP * IN_CH];
__device__ __align__(256) __nv_bfloat16 g_w_hi[OUT_CH * KTOT];   // [oc][rs][c]
__device__ __align__(256) __nv_bfloat16 g_w_lo[OUT_CH * KTOT];
__device__ float g_scale[OUT_CH];
__device__ float g_bias[OUT_CH];

// ---------------------------------------------------------------------------
// Helpers
// ---------------------------------------------------------------------------
__device__ __forceinline__ uint32_t smem_u32(const void* p) {
    uint32_t a;
    asm("{ .reg .u64 t; cvta.to.shared.u64 t, %1; cvt.u32.u64 %0, t; }" : "=r"(a) : "l"(p));
    return a;
}
__device__ __forceinline__ uint32_t sw128(uint32_t off) {
    return off ^ ((off >> 3) & 0x70);
}
__device__ __forceinline__ void cp16(uint32_t dst, const __nv_bfloat16* src) {
    asm volatile("cp.async.cg.shared.global [%0], [%1], 16;"
                 :: "r"(dst), "l"(__cvta_generic_to_global(src)));
}

#define MBAR_INIT(a, c) \
    asm volatile("mbarrier.init.shared.b64 [%0], %1;" :: "r"(a), "r"(c) : "memory")
#define CP_MBAR_ARRIVE(a) \
    asm volatile("cp.async.mbarrier.arrive.noinc.shared.b64 [%0];" :: "r"(a) : "memory")
#define MBAR_ARRIVE(a) \
    asm volatile("mbarrier.arrive.shared.b64 _, [%0];" :: "r"(a) : "memory")

#define MBAR_WAIT(mbar, parity) do {                                              \
    uint32_t _m = (uint32_t)(mbar);                                               \
    uint32_t _p = (uint32_t)(parity);                                             \
    uint32_t _done;                                                               \
    asm volatile(                                                                 \
        "{\n\t.reg .pred p;\n\t"                                                  \
        "mbarrier.try_wait.parity.acquire.cta.shared::cta.b64 p, [%1], %2;\n\t"   \
        "selp.b32 %0, 1, 0, p;\n\t}"                                              \
        : "=r"(_done) : "r"(_m), "r"(_p) : "memory");                             \
    if (!_done) {                                                                 \
        asm volatile(                                                             \
            "{\n\t.reg .pred P1;\n\t"                                             \
            "WAIT_LOOP_%=:\n\t"                                                   \
            "mbarrier.try_wait.parity.acquire.cta.shared::cta.b64 P1, [%0], %1, 0x989680;\n\t" \
            "@P1 bra.uni WAIT_DONE_%=;\n\t"                                       \
            "bra.uni WAIT_LOOP_%=;\n\t"                                           \
            "WAIT_DONE_%=:\n\t}"                                                  \
            :: "r"(_m), "r"(_p) : "memory");                                      \
    }                                                                             \
} while (0)

__device__ __forceinline__ void ldsm4(uint32_t* r, uint32_t addr) {
    asm volatile("ldmatrix.sync.aligned.m8n8.x4.shared.b16 {%0,%1,%2,%3}, [%4];"
                 : "=r"(r[0]), "=r"(r[1]), "=r"(r[2]), "=r"(r[3]) : "r"(addr));
}
__device__ __forceinline__ void mma16816(float* d, const uint32_t* a, const uint32_t* b) {
    asm volatile(
        "mma.sync.aligned.m16n8k16.row.col.f32.bf16.bf16.f32 "
        "{%0,%1,%2,%3}, {%4,%5,%6,%7}, {%8,%9}, {%0,%1,%2,%3};"
        : "+f"(d[0]), "+f"(d[1]), "+f"(d[2]), "+f"(d[3])
        : "r"(a[0]), "r"(a[1]), "r"(a[2]), "r"(a[3]), "r"(b[0]), "r"(b[1]));
}

// ---------------------------------------------------------------------------
// Kernel 1: weights — MRR phase -> bf16 hi/lo in [oc][rs][c] order + BN fold
// ---------------------------------------------------------------------------
__global__ void prep_kernel(const float* __restrict__ phase,
                            const float* __restrict__ gamma,
                            const float* __restrict__ beta,
                            const float* __restrict__ rmean,
                            const float* __restrict__ rvar) {
    int idx = blockIdx.x * 256 + threadIdx.x;
    if (idx < OUT_CH * KTOT) {
        int oc  = idx / KTOT;
        int kp  = idx - oc * KTOT;     // rs*128 + c
        int rs  = kp >> 7;
        int c   = kp & 127;
        int korig = c * 9 + rs;        // original (c,r,s) K order used by the blocks
        int gy = oc >> 3, i = oc & 7;
        int gx = korig >> 3, j = korig & 7;
        float phi = phase[((gy * 144 + gx) * 8 + i) * 8 + j];
        float cc = cosf(phi);
        float ar = MRR_A * MRR_R;
        float num = MRR_A * MRR_A - 2.0f * ar * cc + MRR_R * MRR_R;
        float den = 1.0f - 2.0f * ar * cc + ar * ar;
        float tr = num / den;
        __nv_bfloat16 hi = __float2bfloat16(tr);
        g_w_hi[idx] = hi;
        g_w_lo[idx] = __float2bfloat16(tr - __bfloat162float(hi));
    }
    if (idx < OUT_CH) {
        float inv = gamma[idx] * rsqrtf(rvar[idx] + 1e-5f);
        g_scale[idx] = inv;
        g_bias[idx]  = beta[idx] - rmean[idx] * inv;
    }
}

// ---------------------------------------------------------------------------
// Kernel 2: x NCHW fp32 -> padded NHWC bf16 hi/lo (smem transpose)
// ---------------------------------------------------------------------------
__global__ void __launch_bounds__(256)
xprep_kernel(const float* __restrict__ x) {
    __shared__ float tile[IN_CH][HW + 1];
    const int n = blockIdx.x, h = blockIdx.y;
    const int tid = threadIdx.x;
    const float* xb = x + (size_t)n * IN_CH * HWSQ + h * HW;
    #pragma unroll 4
    for (int i = tid; i < IN_CH * HW; i += 256) {
        int c = i / HW, w = i - c * HW;
        tile[c][w] = xb[(size_t)c * HWSQ + w];
    }
    __syncthreads();
    const size_t obase = (((size_t)n * HWP + h + 1) * HWP + 1) * IN_CH;
    #pragma unroll 4
    for (int i = tid; i < HW * IN_CH; i += 256) {
        int w = i >> 7, c = i & 127;
        float v = tile[c][w];
        __nv_bfloat16 hi = __float2bfloat16(v);
        g_x_hi[obase + (size_t)w * IN_CH + c] = hi;
        g_x_lo[obase + (size_t)w * IN_CH + c] = __float2bfloat16(v - __bfloat162float(hi));
    }
}

// ---------------------------------------------------------------------------
// Kernel 3: implicit-GEMM conv, mbarrier 3-stage pipeline, bf16x3 mma.sync
//   512 threads, warp grid 4x4, warp tile 32x32, cross-chunk fragment pipeline
//   free[] barriers warp-counted (16 arrivals), released at last stage read
// ---------------------------------------------------------------------------
__global__ void __launch_bounds__(NTHREADS, 1)
conv_kernel(float* __restrict__ out) {
    extern __shared__ char smem[];
    const uint32_t sb = smem_u32(smem);
    const uint32_t mb = sb + OFF_MBAR;
    const int tid = threadIdx.x;
    const int wid = tid >> 5;
    const int lid = tid & 31;
    const int p0  = blockIdx.y * MT;   // pixel tile base
    const int oc0 = blockIdx.x * NT;   // oc tile base (adjacent bids share A in L2)

    const int warpM = wid >> 2;        // 0..3 -> 32-pixel band
    const int warpN = wid & 3;         // 0..3 -> 32-oc band

    if (tid == 0) {
        #pragma unroll
        for (int s = 0; s < STAGES; ++s) {
            MBAR_INIT(mb + s * 8, NTHREADS);        // full[s]: per-thread cp arrivals
            MBAR_INIT(mb + 24 + s * 8, NWARPS);     // free[s]: per-warp arrivals
        }
    }
    if (tid < NT) {
        ((float*)(smem + OFF_SCALE))[tid] = g_scale[oc0 + tid];
        ((float*)(smem + OFF_BIAS))[tid]  = g_bias[oc0 + tid];
    }
    __syncthreads();   // mbarrier init + scale/bias visible; only CTA-wide barrier

    // ---- per-thread load assignment: 4 threads per 128B row, 2 segs each --
    const int lrow = tid >> 2;                 // 0..127 (pixel row & oc row)
    const int segb = (tid & 3) * 2;            // 16B-segment start (of 8)
    const int pg   = p0 + lrow;
    const int nimg = pg / HWSQ;
    const int rem  = pg - nimg * HWSQ;
    const int oh   = rem / HW;
    const int ow   = rem - oh * HW;
    const __nv_bfloat16* xhi_n = g_x_hi + (size_t)nimg * (HWP * HWP * IN_CH);
    const __nv_bfloat16* xlo_n = g_x_lo + (size_t)nimg * (HWP * HWP * IN_CH);
    uint32_t dsts[2];
    #pragma unroll
    for (int j = 0; j < 2; ++j)
        dsts[j] = sw128((uint32_t)(lrow * 128 + (segb + j) * 16));

    auto issue_loads = [&](int kc, int st) {
        const int rs = kc >> 1, half = kc & 1;
        const int r = rs / 3, s = rs - r * 3;
        const size_t aoff = (((size_t)(oh + r) * HWP) + (ow + s)) * IN_CH
                            + half * 64 + segb * 8;
        const __nv_bfloat16* ahi = xhi_n + aoff;
        const __nv_bfloat16* alo = xlo_n + aoff;
        const size_t boff = ((size_t)(oc0 + lrow) * 9 + rs) * 128
                            + half * 64 + segb * 8;
        const __nv_bfloat16* bhi = g_w_hi + boff;
        const __nv_bfloat16* blo = g_w_lo + boff;
        const uint32_t s0 = sb + st * STG_BYTES;
        #pragma unroll
        for (int j = 0; j < 2; ++j) {
            cp16(s0 + SOFF_AHI + dsts[j], ahi + j * 8);
            cp16(s0 + SOFF_ALO + dsts[j], alo + j * 8);
            cp16(s0 + SOFF_BHI + dsts[j], bhi + j * 8);
            cp16(s0 + SOFF_BLO + dsts[j], blo + j * 8);
        }
    };

    float acc[2][4][4];
    #pragma unroll
    for (int f = 0; f < 2; ++f)
        #pragma unroll
        for (int g = 0; g < 4; ++g)
            #pragma unroll
            for (int e = 0; e < 4; ++e) acc[f][g][e] = 0.0f;

    // ldmatrix lane mapping
    const int li = lid >> 3;
    const int lj = lid & 7;
    const int a_row = warpM * 32 + (li & 1) * 8 + lj;
    const int a_kof = (li >> 1) * 8;
    const int b_row = warpN * 32 + (li >> 1) * 8 + lj;
    const int b_kof = (li & 1) * 8;

    // double-buffered fragments (alternating across the whole K loop)
    uint32_t Ahi[2][2][4], Alo[2][2][4], Bhi[2][4][2], Blo[2][4][2];

    auto load_frags = [&](uint32_t s0, int ks, int bu) {
        #pragma unroll
        for (int f = 0; f < 2; ++f) {
            uint32_t off = sw128((uint32_t)((a_row + f * 16) * 128 +
                                            (ks * 16 + a_kof) * 2));
            ldsm4(Ahi[bu][f], s0 + SOFF_AHI + off);
            ldsm4(Alo[bu][f], s0 + SOFF_ALO + off);
        }
        #pragma unroll
        for (int h = 0; h < 2; ++h) {
            uint32_t off = sw128((uint32_t)((b_row + h * 16) * 128 +
                                            (ks * 16 + b_kof) * 2));
            uint32_t t[4];
            ldsm4(t, s0 + SOFF_BHI + off);
            Bhi[bu][h*2+0][0] = t[0]; Bhi[bu][h*2+0][1] = t[1];
            Bhi[bu][h*2+1][0] = t[2]; Bhi[bu][h*2+1][1] = t[3];
            ldsm4(t, s0 + SOFF_BLO + off);
            Blo[bu][h*2+0][0] = t[0]; Blo[bu][h*2+0][1] = t[1];
            Blo[bu][h*2+1][0] = t[2]; Blo[bu][h*2+1][1] = t[3];
        }
    };

    auto mma_block = [&](int bu) {
        #pragma unroll
        for (int f = 0; f < 2; ++f)
            #pragma unroll
            for (int g = 0; g < 4; ++g) {
                mma16816(acc[f][g], Ahi[bu][f], Bhi[bu][g]);
                mma16816(acc[f][g], Ahi[bu][f], Blo[bu][g]);
                mma16816(acc[f][g], Alo[bu][f], Bhi[bu][g]);
            }
    };

    // ---- pipeline prologue: fill stages 0 and 1; preload chunk0 ks0 frags --
    issue_loads(0, 0); CP_MBAR_ARRIVE(mb + 0);
    issue_loads(1, 1); CP_MBAR_ARRIVE(mb + 8);
    MBAR_WAIT(mb + 0, 0);
    load_frags(sb, 0, 0);

    for (int kc = 0; kc < NCHUNK; ++kc) {
        const int rnd = kc / 3;
        const int s   = kc - rnd * 3;
        const uint32_t s0 = sb + s * STG_BYTES;

        // ks = 0
        load_frags(s0, 1, 1);
        mma_block(0);
        // ks = 1
        load_frags(s0, 2, 0);
        mma_block(1);
        // ks = 2: last stage-s ldsm -> release stage early (warp-counted)
        load_frags(s0, 3, 1);
        if (lid == 0) MBAR_ARRIVE(mb + 24 + s * 8);
        mma_block(0);
        // ks = 3: cross-chunk prefetch (next chunk's ks0 from next stage)
        if (kc + 1 < NCHUNK) {
            const int rn1 = (kc + 1) / 3;
            const int sn1 = (kc + 1) - rn1 * 3;
            MBAR_WAIT(mb + sn1 * 8, rn1 & 1);            // usually already fired
            load_frags(sb + sn1 * STG_BYTES, 0, 0);      // next chunk ks0 -> buf 0
        }
        mma_block(1);

        // refill: stage (kc+2)%3 with chunk kc+2
        const int kn = kc + 2;
        if (kn < NCHUNK) {
            const int rn = kn / 3;
            const int sn = kn - rn * 3;
            if (kn >= STAGES)                  // stage sn last released in chunk kn-3
                MBAR_WAIT(mb + 24 + sn * 8, (rn - 1) & 1);
            issue_loads(kn, sn);
            CP_MBAR_ARRIVE(mb + sn * 8);
        }
    }

    // ---- epilogue: BN + ReLU6 + stores ------------------------------------
    const float* ss = (const float*)(smem + OFF_SCALE);
    const float* bb = (const float*)(smem + OFF_BIAS);

    #pragma unroll
    for (int f = 0; f < 2; ++f) {
        int p1 = p0 + warpM * 32 + f * 16 + (lid >> 2);
        int p2 = p1 + 8;
        int n1 = p1 / HWSQ, r1 = p1 - n1 * HWSQ;
        int n2 = p2 / HWSQ, r2 = p2 - n2 * HWSQ;
        float* o1 = out + (size_t)n1 * OUT_CH * HWSQ + r1;
        float* o2 = out + (size_t)n2 * OUT_CH * HWSQ + r2;
        #pragma unroll
        for (int g = 0; g < 4; ++g) {
            int cl = warpN * 32 + g * 8 + (lid & 3) * 2;
            int ocA = oc0 + cl, ocB = ocA + 1;
            float sA = ss[cl], bA = bb[cl];
            float sB = ss[cl + 1], bB = bb[cl + 1];
            float v0 = fminf(fmaxf(acc[f][g][0] * sA + bA, 0.0f), 6.0f);
            float v1 = fminf(fmaxf(acc[f][g][1] * sB + bB, 0.0f), 6.0f);
            float v2 = fminf(fmaxf(acc[f][g][2] * sA + bA, 0.0f), 6.0f);
            float v3 = fminf(fmaxf(acc[f][g][3] * sB + bB, 0.0f), 6.0f);
            o1[(size_t)ocA * HWSQ] = v0;
            o1[(size_t)ocB * HWSQ] = v1;
            o2[(size_t)ocA * HWSQ] = v2;
            o2[(size_t)ocB * HWSQ] = v3;
        }
    }
}

// ---------------------------------------------------------------------------
// Launch
// ---------------------------------------------------------------------------
extern "C" void kernel_launch(void* const* d_in, const int* in_sizes, int n_in,
                              void* d_out, int out_size) {
    const float* x     = (const float*)d_in[0];
    const float* phase = (const float*)d_in[1];
    const float* gamma = (const float*)d_in[2];
    const float* beta  = (const float*)d_in[3];
    const float* rmean = (const float*)d_in[4];
    const float* rvar  = (const float*)d_in[5];
    float* out = (float*)d_out;

    cudaFuncSetAttribute(conv_kernel,
                         cudaFuncAttributeMaxDynamicSharedMemorySize, SMEM_TOTAL);

    prep_kernel<<<(OUT_CH * KTOT + 255) / 256, 256>>>(phase, gamma, beta, rmean, rvar);
    dim3 xg(64, HW);
    xprep_kernel<<<xg, 256>>>(x);

    dim3 grid(OUT_CH / NT, PIXTOT / MT);   // (2, 1568): oc-major for A-tile L2 reuse
    conv_kernel<<<grid, NTHREADS, SMEM_TOTAL>>>(out);
}